// round 1
// baseline (speedup 1.0000x reference)
#include <cuda_runtime.h>
#include <cuda_bf16.h>
#include <math.h>

// Problem constants (shape-fixed per reference)
#define NN   50000
#define NE   800000
#define DIM  128
#define NH   8
#define HD   16

// -------- scratch in __device__ globals (no runtime allocation allowed) -----
__device__ float g_Q[NN * DIM];
__device__ float g_K[NN * DIM];
__device__ float g_V[NN * DIM];
__device__ float g_E[(size_t)NE * DIM];   // 409.6 MB
__device__ float g_Z[NN * NH];

// ---------------- packed f32x2 helpers (sm_100+ only via PTX) ---------------
__device__ __forceinline__ unsigned long long dup2(float x) {
    unsigned long long r;
    asm("mov.b64 %0, {%1, %1};" : "=l"(r) : "f"(x));
    return r;
}
__device__ __forceinline__ void ffma2(unsigned long long& a,
                                      unsigned long long b,
                                      unsigned long long c) {
    asm("fma.rn.f32x2 %0, %1, %2, %0;" : "+l"(a) : "l"(b), "l"(c));
}
union F2U { float2 f; unsigned long long u; };

// ------------------- GEMM: C[M,128] = X[M,128] @ W[128,128] + b -------------
// Block tile 128x128, 256 threads, each thread: 8 rows x 8 cols (4 f32x2 pairs/row).
#define XS_PITCH 133   // scalar loads only; 8*133 % 32 != 0 avoids bank conflicts
#define WS_PITCH 132   // 132*4 = 528 bytes, 16B-aligned rows for LDS.128

__global__ __launch_bounds__(256, 1)
void gemm128_kernel(const float* __restrict__ X, const float* __restrict__ W,
                    const float* __restrict__ bias, float* __restrict__ C, int M) {
    extern __shared__ float sm[];
    float* Xs = sm;                       // [128][133]
    float* Ws = sm + 128 * XS_PITCH;      // [128][132]

    const int tid  = threadIdx.x;
    const int row0 = blockIdx.x * 128;

    // Load W tile (128x128) into smem
    for (int i = tid; i < 128 * 32; i += 256) {
        int r  = i >> 5;
        int c4 = (i & 31) << 2;
        float4 w = *(const float4*)(W + r * DIM + c4);
        Ws[r * WS_PITCH + c4 + 0] = w.x;
        Ws[r * WS_PITCH + c4 + 1] = w.y;
        Ws[r * WS_PITCH + c4 + 2] = w.z;
        Ws[r * WS_PITCH + c4 + 3] = w.w;
    }
    // Load X tile (128 rows, guard tail)
    for (int i = tid; i < 128 * 32; i += 256) {
        int r  = i >> 5;
        int c4 = (i & 31) << 2;
        int gr = row0 + r;
        float4 v = make_float4(0.f, 0.f, 0.f, 0.f);
        if (gr < M) v = *(const float4*)(X + (size_t)gr * DIM + c4);
        Xs[r * XS_PITCH + c4 + 0] = v.x;
        Xs[r * XS_PITCH + c4 + 1] = v.y;
        Xs[r * XS_PITCH + c4 + 2] = v.z;
        Xs[r * XS_PITCH + c4 + 3] = v.w;
    }
    __syncthreads();

    const int tr = (tid >> 4) * 8;   // row base within tile
    const int tc = (tid & 15) * 8;   // col base

    // init accumulators with bias pairs
    unsigned long long acc[8][4];
    {
        unsigned long long binit[4];
#pragma unroll
        for (int j = 0; j < 4; j++) {
            F2U u;
            u.f = *(const float2*)(bias + tc + 2 * j);
            binit[j] = u.u;
        }
#pragma unroll
        for (int r = 0; r < 8; r++)
#pragma unroll
            for (int j = 0; j < 4; j++) acc[r][j] = binit[j];
    }

#pragma unroll 4
    for (int k = 0; k < 128; k++) {
        // 8 W values = 4 packed pairs, via two LDS.128
        ulonglong2 wa = *(const ulonglong2*)(Ws + k * WS_PITCH + tc);
        ulonglong2 wb = *(const ulonglong2*)(Ws + k * WS_PITCH + tc + 4);
        unsigned long long w2[4] = { wa.x, wa.y, wb.x, wb.y };
#pragma unroll
        for (int r = 0; r < 8; r++) {
            unsigned long long x2 = dup2(Xs[(tr + r) * XS_PITCH + k]);
            ffma2(acc[r][0], w2[0], x2);
            ffma2(acc[r][1], w2[1], x2);
            ffma2(acc[r][2], w2[2], x2);
            ffma2(acc[r][3], w2[3], x2);
        }
    }

    // store
#pragma unroll
    for (int r = 0; r < 8; r++) {
        int gr = row0 + tr + r;
        if (gr < M) {
#pragma unroll
            for (int j = 0; j < 4; j++) {
                F2U u; u.u = acc[r][j];
                *(float2*)(C + (size_t)gr * DIM + tc + 2 * j) = u.f;
            }
        }
    }
}

// --------------------------- edge scatter kernel ----------------------------
__device__ __forceinline__ void red4(float* p, float a, float b, float c, float d) {
    asm volatile("red.global.add.v4.f32 [%0], {%1, %2, %3, %4};"
                 :: "l"(p), "f"(a), "f"(b), "f"(c), "f"(d) : "memory");
}

__global__ __launch_bounds__(256)
void edge_kernel(const int* __restrict__ ei, const float* __restrict__ E,
                 float* __restrict__ wV, int nE) {
    int t = blockIdx.x * blockDim.x + threadIdx.x;
    if (t >= nE * NH) return;
    int e = t >> 3;
    int h = t & 7;

    int src = ei[e];
    int dst = ei[nE + e];

    const float4* Kp = (const float4*)(g_K + (size_t)src * DIM + h * HD);
    const float4* Qp = (const float4*)(g_Q + (size_t)dst * DIM + h * HD);
    const float4* Ep = (const float4*)(E + (size_t)e * DIM + h * HD);

    float s = 0.f;
#pragma unroll
    for (int i = 0; i < 4; i++) {
        float4 kv = Kp[i];
        float4 qv = Qp[i];
        float4 ev = Ep[i];
        s = fmaf(kv.x * qv.x, ev.x, s);
        s = fmaf(kv.y * qv.y, ev.y, s);
        s = fmaf(kv.z * qv.z, ev.z, s);
        s = fmaf(kv.w * qv.w, ev.w, s);
    }
    s *= 0.25f;                          // 1/sqrt(16)
    s = fminf(fmaxf(s, -5.f), 5.f);
    s = expf(s);

    const float4* Vp = (const float4*)(g_V + (size_t)src * DIM + h * HD);
    float* out = wV + (size_t)dst * DIM + h * HD;
#pragma unroll
    for (int i = 0; i < 4; i++) {
        float4 v = Vp[i];
        red4(out + 4 * i, v.x * s, v.y * s, v.z * s, v.w * s);
    }
    atomicAdd(&g_Z[dst * NH + h], s);
}

// ----------------------------- normalize ------------------------------------
__global__ __launch_bounds__(256)
void normalize_kernel(float* __restrict__ out, int n) {
    int i = blockIdx.x * blockDim.x + threadIdx.x;
    if (i >= n) return;
    int node = i >> 7;
    int h    = (i >> 4) & 7;
    float z = g_Z[node * NH + h];
    out[i] = out[i] / (z + 1e-6f);
}

// ----------------------------- launcher -------------------------------------
extern "C" void kernel_launch(void* const* d_in, const int* in_sizes, int n_in,
                              void* d_out, int out_size) {
    const float* x   = (const float*)d_in[0];
    const float* ea  = (const float*)d_in[1];
    const int*   ei  = (const int*)d_in[2];
    const float* Wq  = (const float*)d_in[3];
    const float* bq  = (const float*)d_in[4];
    const float* Wk  = (const float*)d_in[5];
    const float* bk  = (const float*)d_in[6];
    const float* We  = (const float*)d_in[7];
    const float* be  = (const float*)d_in[8];
    const float* Wv  = (const float*)d_in[9];
    const float* bv  = (const float*)d_in[10];
    float* out = (float*)d_out;

    const int nN = in_sizes[0] / DIM;     // 50000
    const int nE = in_sizes[1] / DIM;     // 800000

    // resolve scratch addresses
    float *pQ, *pK, *pV, *pE, *pZ;
    cudaGetSymbolAddress((void**)&pQ, g_Q);
    cudaGetSymbolAddress((void**)&pK, g_K);
    cudaGetSymbolAddress((void**)&pV, g_V);
    cudaGetSymbolAddress((void**)&pE, g_E);
    cudaGetSymbolAddress((void**)&pZ, g_Z);

    // zero accumulators
    cudaMemsetAsync(d_out, 0, (size_t)out_size * sizeof(float));
    cudaMemsetAsync(pZ, 0, (size_t)nN * NH * sizeof(float));

    const int smem = (128 * XS_PITCH + 128 * WS_PITCH) * sizeof(float);
    cudaFuncSetAttribute(gemm128_kernel, cudaFuncAttributeMaxDynamicSharedMemorySize, smem);

    int gN = (nN + 127) / 128;
    int gE = (nE + 127) / 128;
    gemm128_kernel<<<gN, 256, smem>>>(x, Wq, bq, pQ, nN);
    gemm128_kernel<<<gN, 256, smem>>>(x, Wk, bk, pK, nN);
    gemm128_kernel<<<gN, 256, smem>>>(x, Wv, bv, pV, nN);
    gemm128_kernel<<<gE, 256, smem>>>(ea, We, be, pE, nE);

    int totalEH = nE * NH;
    edge_kernel<<<(totalEH + 255) / 256, 256>>>(ei, pE, out, nE);

    int totalO = nN * DIM;
    normalize_kernel<<<(totalO + 255) / 256, 256>>>(out, totalO);
}

// round 3
// speedup vs baseline: 1.5103x; 1.5103x over previous
#include <cuda_runtime.h>
#include <cuda_bf16.h>
#include <math.h>
#include <stdint.h>

// Problem constants (shape-fixed per reference)
#define NN   50000
#define NE   800000
#define DIM  128
#define NH   8
#define HD   16

// -------- scratch in __device__ globals (no runtime allocation allowed) -----
__device__ float g_Q[NN * DIM];
__device__ float g_K[NN * DIM];
__device__ float g_V[NN * DIM];
__device__ float g_E[(size_t)NE * DIM];   // 409.6 MB
__device__ float g_Z[NN * NH];
// Pre-swizzled bf16 weight images (hi / lo split), 4 matrices (q,k,v,e)
__device__ __nv_bfloat16 g_W1img[4][DIM * DIM];
__device__ __nv_bfloat16 g_W2img[4][DIM * DIM];

// ---------------------------------------------------------------------------
__device__ __forceinline__ uint32_t smem_u32(const void* p) {
    uint32_t a;
    asm("{ .reg .u64 t; cvta.to.shared.u64 t, %1; cvt.u32.u64 %0, t; }"
        : "=r"(a) : "l"(p));
    return a;
}

// Swizzled byte offset inside a 128x128 bf16 tile (row-major rows of 256B).
// 16B unit index u = k>>3 (0..15); low 3 bits XOR'd with (r&7) -> ldmatrix
// phases (8 consecutive rows, same k) hit 8 distinct 16B units = conflict-free.
__device__ __forceinline__ uint32_t soff(int r, int k) {
    uint32_t u = (uint32_t)(k >> 3);
    uint32_t us = (u & 8u) | ((u ^ (uint32_t)(r & 7)) & 7u);
    return (uint32_t)r * 256u + us * 16u + (uint32_t)(k & 7) * 2u;
}

__device__ __forceinline__ void ldsm_x4(uint32_t* r, uint32_t addr) {
    asm volatile("ldmatrix.sync.aligned.m8n8.x4.shared.b16 {%0,%1,%2,%3}, [%4];"
                 : "=r"(r[0]), "=r"(r[1]), "=r"(r[2]), "=r"(r[3]) : "r"(addr));
}

__device__ __forceinline__ void mma16816(float* d, const uint32_t* a,
                                         uint32_t b0, uint32_t b1) {
    asm volatile(
        "mma.sync.aligned.m16n8k16.row.col.f32.bf16.bf16.f32 "
        "{%0,%1,%2,%3}, {%4,%5,%6,%7}, {%8,%9}, {%0,%1,%2,%3};"
        : "+f"(d[0]), "+f"(d[1]), "+f"(d[2]), "+f"(d[3])
        : "r"(a[0]), "r"(a[1]), "r"(a[2]), "r"(a[3]), "r"(b0), "r"(b1));
}

// ---------------- weight prep: fp32 W[k,n] -> swizzled bf16 hi/lo images -----
// Image layout: B operand [N rows][K cols], swizzled via soff.
__global__ __launch_bounds__(256)
void prep_w_kernel(const float* __restrict__ W, __nv_bfloat16* __restrict__ img1,
                   __nv_bfloat16* __restrict__ img2) {
    int i = blockIdx.x * 256 + threadIdx.x;
    if (i >= DIM * DIM) return;
    int k = i >> 7;       // input row (k-dim)
    int n = i & 127;      // input col (n-dim)
    float a = W[i];
    __nv_bfloat16 h = __float2bfloat16(a);
    float lo = a - __bfloat162float(h);
    uint32_t off = soff(n, k);
    *(__nv_bfloat16*)((char*)img1 + off) = h;
    *(__nv_bfloat16*)((char*)img2 + off) = __float2bfloat16(lo);
}

// ------------------- HMMA GEMM: C[M,128] = X[M,128]@W + b -------------------
// smem: bias (512B) | A1 | A2 | W1 | W2  (each tile 32KB)
#define SM_BIAS  0
#define SM_A1    1024
#define SM_A2    (1024 + 32768)
#define SM_W1    (1024 + 65536)
#define SM_W2    (1024 + 98304)
#define SM_TOTAL (1024 + 131072)

__global__ __launch_bounds__(256, 1)
void gemm_mma_kernel(const float* __restrict__ X,
                     const __nv_bfloat16* __restrict__ W1img,
                     const __nv_bfloat16* __restrict__ W2img,
                     const float* __restrict__ bias,
                     float* __restrict__ C, int M) {
    extern __shared__ char smem[];
    const uint32_t sb = smem_u32(smem);
    const int tid = threadIdx.x;
    const int wid = tid >> 5;
    const int lid = tid & 31;
    const int row0 = blockIdx.x * 128;

    // copy pre-swizzled weight images into smem (linear copy preserves layout)
    {
        const int4* s1 = (const int4*)W1img;
        const int4* s2 = (const int4*)W2img;
        int4* d1 = (int4*)(smem + SM_W1);
        int4* d2 = (int4*)(smem + SM_W2);
        #pragma unroll
        for (int i = tid; i < 2048; i += 256) {
            d1[i] = s1[i];
            d2[i] = s2[i];
        }
    }
    if (tid < 128) *(float*)(smem + SM_BIAS + tid * 4) = bias[tid];

    // load + split-convert A tile into swizzled smem (hi -> A1, lo -> A2)
    for (int i = tid; i < 128 * 32; i += 256) {
        int r  = i >> 5;
        int k4 = (i & 31) << 2;
        int gr = row0 + r;
        float4 v = make_float4(0.f, 0.f, 0.f, 0.f);
        if (gr < M) v = *(const float4*)(X + (size_t)gr * DIM + k4);
        __nv_bfloat16 hx = __float2bfloat16(v.x);
        __nv_bfloat16 hy = __float2bfloat16(v.y);
        __nv_bfloat16 hz = __float2bfloat16(v.z);
        __nv_bfloat16 hw = __float2bfloat16(v.w);
        __nv_bfloat162 hp0; hp0.x = hx; hp0.y = hy;
        __nv_bfloat162 hp1; hp1.x = hz; hp1.y = hw;
        __nv_bfloat162 lp0 = __floats2bfloat162_rn(v.x - __bfloat162float(hx),
                                                   v.y - __bfloat162float(hy));
        __nv_bfloat162 lp1 = __floats2bfloat162_rn(v.z - __bfloat162float(hz),
                                                   v.w - __bfloat162float(hw));
        uint32_t o0 = soff(r, k4);       // k4, k4+2 share a 16B unit
        *(__nv_bfloat162*)(smem + SM_A1 + o0)     = hp0;
        *(__nv_bfloat162*)(smem + SM_A1 + o0 + 4) = hp1;
        *(__nv_bfloat162*)(smem + SM_A2 + o0)     = lp0;
        *(__nv_bfloat162*)(smem + SM_A2 + o0 + 4) = lp1;
    }
    __syncthreads();

    // warp tiling: 2 (M) x 4 (N) warps, each 64x32
    const int wm = (wid >> 2) * 64;   // 0 or 64
    const int wn = (wid & 3) * 32;    // 0,32,64,96

    // per-lane ldmatrix row assignment (identical for A and B)
    const int g  = lid >> 3;                       // 0..3
    const int lr = (lid & 7) | ((g & 1) << 3);     // row-in-16
    const int kq = (g >> 1) << 3;                  // 0 or 8

    float acc[4][4][4];
    #pragma unroll
    for (int i = 0; i < 4; i++)
        #pragma unroll
        for (int j = 0; j < 4; j++)
            #pragma unroll
            for (int t = 0; t < 4; t++) acc[i][j][t] = 0.f;

    const uint32_t aoff[3] = { sb + SM_A1, sb + SM_A2, sb + SM_A1 };
    const uint32_t boff[3] = { sb + SM_W1, sb + SM_W1, sb + SM_W2 };

    #pragma unroll 1
    for (int ph = 0; ph < 3; ph++) {
        const uint32_t ab = aoff[ph];
        const uint32_t bb = boff[ph];
        #pragma unroll
        for (int ks = 0; ks < 8; ks++) {
            const int k0 = ks * 16 + kq;
            uint32_t af[4][4];
            #pragma unroll
            for (int mt = 0; mt < 4; mt++)
                ldsm_x4(af[mt], ab + soff(wm + mt * 16 + lr, k0));
            uint32_t bf[2][4];
            #pragma unroll
            for (int nt2 = 0; nt2 < 2; nt2++)
                ldsm_x4(bf[nt2], bb + soff(wn + nt2 * 16 + lr, k0));
            // bf[nt2] regs: {b0(n lo8), b0(n hi8), b1(n lo8), b1(n hi8)}
            #pragma unroll
            for (int mt = 0; mt < 4; mt++) {
                mma16816(acc[mt][0], af[mt], bf[0][0], bf[0][2]);
                mma16816(acc[mt][1], af[mt], bf[0][1], bf[0][3]);
                mma16816(acc[mt][2], af[mt], bf[1][0], bf[1][2]);
                mma16816(acc[mt][3], af[mt], bf[1][1], bf[1][3]);
            }
        }
    }

    // epilogue: c frag lane l -> rows l/4, l/4+8; cols 2*(l%4), +1
    const float* sBias = (const float*)(smem + SM_BIAS);
    const int cr = lid >> 2;
    const int cc = (lid & 3) * 2;
    #pragma unroll
    for (int mt = 0; mt < 4; mt++) {
        #pragma unroll
        for (int nt = 0; nt < 4; nt++) {
            int col = wn + nt * 8 + cc;
            float b0 = sBias[col], b1 = sBias[col + 1];
            int r1 = row0 + wm + mt * 16 + cr;
            if (r1 < M) {
                float2 o; o.x = acc[mt][nt][0] + b0; o.y = acc[mt][nt][1] + b1;
                *(float2*)(C + (size_t)r1 * DIM + col) = o;
            }
            int r2 = r1 + 8;
            if (r2 < M) {
                float2 o; o.x = acc[mt][nt][2] + b0; o.y = acc[mt][nt][3] + b1;
                *(float2*)(C + (size_t)r2 * DIM + col) = o;
            }
        }
    }
}

// --------------------------- edge scatter kernel ----------------------------
__device__ __forceinline__ void red4(float* p, float a, float b, float c, float d) {
    asm volatile("red.global.add.v4.f32 [%0], {%1, %2, %3, %4};"
                 :: "l"(p), "f"(a), "f"(b), "f"(c), "f"(d) : "memory");
}

__global__ __launch_bounds__(256)
void edge_kernel(const int* __restrict__ ei, const float* __restrict__ E,
                 float* __restrict__ wV, int nE) {
    int t = blockIdx.x * blockDim.x + threadIdx.x;
    if (t >= nE * NH) return;
    int e = t >> 3;
    int h = t & 7;

    int src = __ldg(ei + e);
    int dst = __ldg(ei + nE + e);

    const float4* Kp = (const float4*)(g_K + (size_t)src * DIM + h * HD);
    const float4* Qp = (const float4*)(g_Q + (size_t)dst * DIM + h * HD);
    const float4* Ep = (const float4*)(E + (size_t)e * DIM + h * HD);

    float s = 0.f;
#pragma unroll
    for (int i = 0; i < 4; i++) {
        float4 kv = Kp[i];
        float4 qv = Qp[i];
        float4 ev = Ep[i];
        s = fmaf(kv.x * qv.x, ev.x, s);
        s = fmaf(kv.y * qv.y, ev.y, s);
        s = fmaf(kv.z * qv.z, ev.z, s);
        s = fmaf(kv.w * qv.w, ev.w, s);
    }
    s *= 0.25f;                          // 1/sqrt(16)
    s = fminf(fmaxf(s, -5.f), 5.f);
    s = expf(s);

    const float4* Vp = (const float4*)(g_V + (size_t)src * DIM + h * HD);
    float* out = wV + (size_t)dst * DIM + h * HD;
#pragma unroll
    for (int i = 0; i < 4; i++) {
        float4 v = Vp[i];
        red4(out + 4 * i, v.x * s, v.y * s, v.z * s, v.w * s);
    }
    atomicAdd(&g_Z[dst * NH + h], s);
}

// ----------------------------- normalize ------------------------------------
__global__ __launch_bounds__(256)
void normalize_kernel(float* __restrict__ out, int n) {
    int i = blockIdx.x * blockDim.x + threadIdx.x;
    if (i >= n) return;
    int node = i >> 7;
    int h    = (i >> 4) & 7;
    float z = g_Z[node * NH + h];
    out[i] = out[i] / (z + 1e-6f);
}

// ----------------------------- launcher -------------------------------------
extern "C" void kernel_launch(void* const* d_in, const int* in_sizes, int n_in,
                              void* d_out, int out_size) {
    const float* x   = (const float*)d_in[0];
    const float* ea  = (const float*)d_in[1];
    const int*   ei  = (const int*)d_in[2];
    const float* Wq  = (const float*)d_in[3];
    const float* bq  = (const float*)d_in[4];
    const float* Wk  = (const float*)d_in[5];
    const float* bk  = (const float*)d_in[6];
    const float* We  = (const float*)d_in[7];
    const float* be  = (const float*)d_in[8];
    const float* Wv  = (const float*)d_in[9];
    const float* bv  = (const float*)d_in[10];
    float* out = (float*)d_out;

    const int nN = in_sizes[0] / DIM;     // 50000
    const int nE = in_sizes[1] / DIM;     // 800000

    float *pQ, *pK, *pV, *pE, *pZ;
    __nv_bfloat16 *pW1, *pW2;
    cudaGetSymbolAddress((void**)&pQ, g_Q);
    cudaGetSymbolAddress((void**)&pK, g_K);
    cudaGetSymbolAddress((void**)&pV, g_V);
    cudaGetSymbolAddress((void**)&pE, g_E);
    cudaGetSymbolAddress((void**)&pZ, g_Z);
    cudaGetSymbolAddress((void**)&pW1, g_W1img);
    cudaGetSymbolAddress((void**)&pW2, g_W2img);

    cudaMemsetAsync(d_out, 0, (size_t)out_size * sizeof(float));
    cudaMemsetAsync(pZ, 0, (size_t)nN * NH * sizeof(float));

    // weight prep (q=0, k=1, v=2, e=3)
    const float* Ws[4] = { Wq, Wk, Wv, We };
    for (int m = 0; m < 4; m++)
        prep_w_kernel<<<64, 256>>>(Ws[m], pW1 + m * DIM * DIM, pW2 + m * DIM * DIM);

    cudaFuncSetAttribute(gemm_mma_kernel, cudaFuncAttributeMaxDynamicSharedMemorySize, SM_TOTAL);

    int gN = (nN + 127) / 128;
    int gE = (nE + 127) / 128;
    gemm_mma_kernel<<<gN, 256, SM_TOTAL>>>(x,  pW1 + 0 * DIM * DIM, pW2 + 0 * DIM * DIM, bq, pQ, nN);
    gemm_mma_kernel<<<gN, 256, SM_TOTAL>>>(x,  pW1 + 1 * DIM * DIM, pW2 + 1 * DIM * DIM, bk, pK, nN);
    gemm_mma_kernel<<<gN, 256, SM_TOTAL>>>(x,  pW1 + 2 * DIM * DIM, pW2 + 2 * DIM * DIM, bv, pV, nN);
    gemm_mma_kernel<<<gE, 256, SM_TOTAL>>>(ea, pW1 + 3 * DIM * DIM, pW2 + 3 * DIM * DIM, be, pE, nE);

    int totalEH = nE * NH;
    edge_kernel<<<(totalEH + 255) / 256, 256>>>(ei, pE, out, nE);

    int totalO = nN * DIM;
    normalize_kernel<<<(totalO + 255) / 256, 256>>>(out, totalO);
}

// round 4
// speedup vs baseline: 1.6348x; 1.0824x over previous
#include <cuda_runtime.h>
#include <cuda_bf16.h>
#include <math.h>
#include <stdint.h>

// Problem constants (shape-fixed per reference)
#define NN   50000
#define NE   800000
#define DIM  128
#define NH   8
#define HD   16

// -------- scratch in __device__ globals (no runtime allocation allowed) -----
__device__ float g_Q[NN * DIM];
__device__ float g_K[NN * DIM];
__device__ float g_V[NN * DIM];
__device__ float g_E[(size_t)NE * DIM];   // 409.6 MB
__device__ float g_Z[NN * NH];
// Pre-swizzled bf16 weight images (hi / lo split), 4 matrices (q,k,v,e)
__device__ __nv_bfloat16 g_W1img[4][DIM * DIM];
__device__ __nv_bfloat16 g_W2img[4][DIM * DIM];

// ---------------------------------------------------------------------------
__device__ __forceinline__ uint32_t smem_u32(const void* p) {
    uint32_t a;
    asm("{ .reg .u64 t; cvta.to.shared.u64 t, %1; cvt.u32.u64 %0, t; }"
        : "=r"(a) : "l"(p));
    return a;
}

// Swizzled byte offset inside a 128x128 bf16 tile (row-major rows of 256B).
__device__ __forceinline__ uint32_t soff(int r, int k) {
    uint32_t u = (uint32_t)(k >> 3);
    uint32_t us = (u & 8u) | ((u ^ (uint32_t)(r & 7)) & 7u);
    return (uint32_t)r * 256u + us * 16u + (uint32_t)(k & 7) * 2u;
}

__device__ __forceinline__ void ldsm_x4(uint32_t* r, uint32_t addr) {
    asm volatile("ldmatrix.sync.aligned.m8n8.x4.shared.b16 {%0,%1,%2,%3}, [%4];"
                 : "=r"(r[0]), "=r"(r[1]), "=r"(r[2]), "=r"(r[3]) : "r"(addr));
}

__device__ __forceinline__ void mma16816(float* d, const uint32_t* a,
                                         uint32_t b0, uint32_t b1) {
    asm volatile(
        "mma.sync.aligned.m16n8k16.row.col.f32.bf16.bf16.f32 "
        "{%0,%1,%2,%3}, {%4,%5,%6,%7}, {%8,%9}, {%0,%1,%2,%3};"
        : "+f"(d[0]), "+f"(d[1]), "+f"(d[2]), "+f"(d[3])
        : "r"(a[0]), "r"(a[1]), "r"(a[2]), "r"(a[3]), "r"(b0), "r"(b1));
}

// ---------------- weight prep: fp32 W[k,n] -> swizzled bf16 hi/lo images -----
// One launch covers all 4 matrices (q=0,k=1,v=2,e=3).
__global__ __launch_bounds__(256)
void prep_w_kernel(const float* __restrict__ W0, const float* __restrict__ W1,
                   const float* __restrict__ W2, const float* __restrict__ W3,
                   __nv_bfloat16* __restrict__ img1, __nv_bfloat16* __restrict__ img2) {
    int gi = blockIdx.x * 256 + threadIdx.x;
    if (gi >= 4 * DIM * DIM) return;
    int m = gi >> 14;
    int i = gi & (DIM * DIM - 1);
    const float* W = (m == 0) ? W0 : (m == 1) ? W1 : (m == 2) ? W2 : W3;
    int k = i >> 7;
    int n = i & 127;
    float a = W[i];
    __nv_bfloat16 h = __float2bfloat16(a);
    float lo = a - __bfloat162float(h);
    uint32_t off = soff(n, k);
    *(__nv_bfloat16*)((char*)(img1 + (size_t)m * DIM * DIM) + off) = h;
    *(__nv_bfloat16*)((char*)(img2 + (size_t)m * DIM * DIM) + off) = __float2bfloat16(lo);
}

// ------------------- HMMA GEMM: C[M,128] = X[M,128]@W + b -------------------
#define SM_BIAS  0
#define SM_A1    1024
#define SM_A2    (1024 + 32768)
#define SM_W1    (1024 + 65536)
#define SM_W2    (1024 + 98304)
#define SM_TOTAL (1024 + 131072)

__global__ __launch_bounds__(256, 1)
void gemm_mma_kernel(const float* __restrict__ X,
                     const __nv_bfloat16* __restrict__ W1img,
                     const __nv_bfloat16* __restrict__ W2img,
                     const float* __restrict__ bias,
                     float* __restrict__ C, int M) {
    extern __shared__ char smem[];
    const uint32_t sb = smem_u32(smem);
    const int tid = threadIdx.x;
    const int wid = tid >> 5;
    const int lid = tid & 31;
    const int row0 = blockIdx.x * 128;

    {
        const int4* s1 = (const int4*)W1img;
        const int4* s2 = (const int4*)W2img;
        int4* d1 = (int4*)(smem + SM_W1);
        int4* d2 = (int4*)(smem + SM_W2);
        #pragma unroll
        for (int i = tid; i < 2048; i += 256) {
            d1[i] = s1[i];
            d2[i] = s2[i];
        }
    }
    if (tid < 128) *(float*)(smem + SM_BIAS + tid * 4) = bias[tid];

    for (int i = tid; i < 128 * 32; i += 256) {
        int r  = i >> 5;
        int k4 = (i & 31) << 2;
        int gr = row0 + r;
        float4 v = make_float4(0.f, 0.f, 0.f, 0.f);
        if (gr < M) v = *(const float4*)(X + (size_t)gr * DIM + k4);
        __nv_bfloat16 hx = __float2bfloat16(v.x);
        __nv_bfloat16 hy = __float2bfloat16(v.y);
        __nv_bfloat16 hz = __float2bfloat16(v.z);
        __nv_bfloat16 hw = __float2bfloat16(v.w);
        __nv_bfloat162 hp0; hp0.x = hx; hp0.y = hy;
        __nv_bfloat162 hp1; hp1.x = hz; hp1.y = hw;
        __nv_bfloat162 lp0 = __floats2bfloat162_rn(v.x - __bfloat162float(hx),
                                                   v.y - __bfloat162float(hy));
        __nv_bfloat162 lp1 = __floats2bfloat162_rn(v.z - __bfloat162float(hz),
                                                   v.w - __bfloat162float(hw));
        uint32_t o0 = soff(r, k4);
        *(__nv_bfloat162*)(smem + SM_A1 + o0)     = hp0;
        *(__nv_bfloat162*)(smem + SM_A1 + o0 + 4) = hp1;
        *(__nv_bfloat162*)(smem + SM_A2 + o0)     = lp0;
        *(__nv_bfloat162*)(smem + SM_A2 + o0 + 4) = lp1;
    }
    __syncthreads();

    const int wm = (wid >> 2) * 64;
    const int wn = (wid & 3) * 32;
    const int g  = lid >> 3;
    const int lr = (lid & 7) | ((g & 1) << 3);
    const int kq = (g >> 1) << 3;

    float acc[4][4][4];
    #pragma unroll
    for (int i = 0; i < 4; i++)
        #pragma unroll
        for (int j = 0; j < 4; j++)
            #pragma unroll
            for (int t = 0; t < 4; t++) acc[i][j][t] = 0.f;

    const uint32_t aoff[3] = { sb + SM_A1, sb + SM_A2, sb + SM_A1 };
    const uint32_t boff[3] = { sb + SM_W1, sb + SM_W1, sb + SM_W2 };

    #pragma unroll 1
    for (int ph = 0; ph < 3; ph++) {
        const uint32_t ab = aoff[ph];
        const uint32_t bb = boff[ph];
        #pragma unroll
        for (int ks = 0; ks < 8; ks++) {
            const int k0 = ks * 16 + kq;
            uint32_t af[4][4];
            #pragma unroll
            for (int mt = 0; mt < 4; mt++)
                ldsm_x4(af[mt], ab + soff(wm + mt * 16 + lr, k0));
            uint32_t bf[2][4];
            #pragma unroll
            for (int nt2 = 0; nt2 < 2; nt2++)
                ldsm_x4(bf[nt2], bb + soff(wn + nt2 * 16 + lr, k0));
            #pragma unroll
            for (int mt = 0; mt < 4; mt++) {
                mma16816(acc[mt][0], af[mt], bf[0][0], bf[0][2]);
                mma16816(acc[mt][1], af[mt], bf[0][1], bf[0][3]);
                mma16816(acc[mt][2], af[mt], bf[1][0], bf[1][2]);
                mma16816(acc[mt][3], af[mt], bf[1][1], bf[1][3]);
            }
        }
    }

    const float* sBias = (const float*)(smem + SM_BIAS);
    const int cr = lid >> 2;
    const int cc = (lid & 3) * 2;
    #pragma unroll
    for (int mt = 0; mt < 4; mt++) {
        #pragma unroll
        for (int nt = 0; nt < 4; nt++) {
            int col = wn + nt * 8 + cc;
            float b0 = sBias[col], b1 = sBias[col + 1];
            int r1 = row0 + wm + mt * 16 + cr;
            if (r1 < M) {
                float2 o; o.x = acc[mt][nt][0] + b0; o.y = acc[mt][nt][1] + b1;
                *(float2*)(C + (size_t)r1 * DIM + col) = o;
            }
            int r2 = r1 + 8;
            if (r2 < M) {
                float2 o; o.x = acc[mt][nt][2] + b0; o.y = acc[mt][nt][3] + b1;
                *(float2*)(C + (size_t)r2 * DIM + col) = o;
            }
        }
    }
}

// --------------------------- edge scatter kernel ----------------------------
// Warp-per-edge: lane l owns floats [4l, 4l+4) of the 128-float row.
// head h = l>>2, 16B chunk = l&3. All K/Q/E/V accesses are fully coalesced
// (one LDG.128 per operand per edge, 4 lines each).
__device__ __forceinline__ void red4(float* p, float a, float b, float c, float d) {
    asm volatile("red.global.add.v4.f32 [%0], {%1, %2, %3, %4};"
                 :: "l"(p), "f"(a), "f"(b), "f"(c), "f"(d) : "memory");
}

__global__ __launch_bounds__(256)
void edge_kernel(const int* __restrict__ ei, const float* __restrict__ E,
                 float* __restrict__ wV, int nE) {
    const int lid   = threadIdx.x & 31;
    const int warp  = (blockIdx.x * blockDim.x + threadIdx.x) >> 5;
    const int nwarp = (gridDim.x * blockDim.x) >> 5;
    const int h  = lid >> 2;
    const int i4 = lid & 3;

    for (int e = warp; e < nE; e += nwarp) {
        int src = __ldg(ei + e);
        int dst = __ldg(ei + nE + e);

        float4 k  = *(const float4*)(g_K + (size_t)src * DIM + 4 * lid);
        float4 q  = *(const float4*)(g_Q + (size_t)dst * DIM + 4 * lid);
        float4 ev = __ldg((const float4*)(E + (size_t)e * DIM + 4 * lid));

        float t = k.x * q.x * ev.x + k.y * q.y * ev.y
                + k.z * q.z * ev.z + k.w * q.w * ev.w;
        t += __shfl_xor_sync(0xFFFFFFFFu, t, 1);
        t += __shfl_xor_sync(0xFFFFFFFFu, t, 2);
        t *= 0.25f;                          // 1/sqrt(16)
        t = fminf(fmaxf(t, -5.f), 5.f);
        float s = __expf(t);

        float4 v = *(const float4*)(g_V + (size_t)src * DIM + 4 * lid);
        red4(wV + (size_t)dst * DIM + 4 * lid, v.x * s, v.y * s, v.z * s, v.w * s);
        if (i4 == 0) atomicAdd(&g_Z[dst * NH + h], s);
    }
}

// ----------------------------- normalize ------------------------------------
__global__ __launch_bounds__(256)
void normalize_kernel(float* __restrict__ out, int n) {
    int i = blockIdx.x * blockDim.x + threadIdx.x;
    if (i >= n) return;
    int node = i >> 7;
    int h    = (i >> 4) & 7;
    float z = g_Z[node * NH + h];
    out[i] = out[i] / (z + 1e-6f);
}

// ----------------------------- launcher -------------------------------------
extern "C" void kernel_launch(void* const* d_in, const int* in_sizes, int n_in,
                              void* d_out, int out_size) {
    const float* x   = (const float*)d_in[0];
    const float* ea  = (const float*)d_in[1];
    const int*   ei  = (const int*)d_in[2];
    const float* Wq  = (const float*)d_in[3];
    const float* bq  = (const float*)d_in[4];
    const float* Wk  = (const float*)d_in[5];
    const float* bk  = (const float*)d_in[6];
    const float* We  = (const float*)d_in[7];
    const float* be  = (const float*)d_in[8];
    const float* Wv  = (const float*)d_in[9];
    const float* bv  = (const float*)d_in[10];
    float* out = (float*)d_out;

    const int nN = in_sizes[0] / DIM;     // 50000
    const int nE = in_sizes[1] / DIM;     // 800000

    float *pQ, *pK, *pV, *pE, *pZ;
    __nv_bfloat16 *pW1, *pW2;
    cudaGetSymbolAddress((void**)&pQ, g_Q);
    cudaGetSymbolAddress((void**)&pK, g_K);
    cudaGetSymbolAddress((void**)&pV, g_V);
    cudaGetSymbolAddress((void**)&pE, g_E);
    cudaGetSymbolAddress((void**)&pZ, g_Z);
    cudaGetSymbolAddress((void**)&pW1, g_W1img);
    cudaGetSymbolAddress((void**)&pW2, g_W2img);

    cudaMemsetAsync(d_out, 0, (size_t)out_size * sizeof(float));
    cudaMemsetAsync(pZ, 0, (size_t)nN * NH * sizeof(float));

    // weight prep: q,k,v,e in one launch
    prep_w_kernel<<<(4 * DIM * DIM + 255) / 256, 256>>>(Wq, Wk, Wv, We, pW1, pW2);

    cudaFuncSetAttribute(gemm_mma_kernel, cudaFuncAttributeMaxDynamicSharedMemorySize, SM_TOTAL);

    int gN = (nN + 127) / 128;
    int gE = (nE + 127) / 128;
    gemm_mma_kernel<<<gN, 256, SM_TOTAL>>>(x,  pW1 + 0 * DIM * DIM, pW2 + 0 * DIM * DIM, bq, pQ, nN);
    gemm_mma_kernel<<<gN, 256, SM_TOTAL>>>(x,  pW1 + 1 * DIM * DIM, pW2 + 1 * DIM * DIM, bk, pK, nN);
    gemm_mma_kernel<<<gN, 256, SM_TOTAL>>>(x,  pW1 + 2 * DIM * DIM, pW2 + 2 * DIM * DIM, bv, pV, nN);
    gemm_mma_kernel<<<gE, 256, SM_TOTAL>>>(ea, pW1 + 3 * DIM * DIM, pW2 + 3 * DIM * DIM, be, pE, nE);

    // warp-per-edge scatter: 4096 blocks * 8 warps, grid-stride over edges
    edge_kernel<<<4096, 256>>>(ei, pE, out, nE);

    int totalO = nN * DIM;
    normalize_kernel<<<(totalO + 255) / 256, 256>>>(out, totalO);
}

// round 5
// speedup vs baseline: 2.6352x; 1.6120x over previous
#include <cuda_runtime.h>
#include <cuda_bf16.h>
#include <math.h>
#include <stdint.h>

// Problem constants (shape-fixed per reference)
#define NN   50000
#define NE   800000
#define DIM  128
#define NH   8
#define HD   16

// -------- scratch in __device__ globals (no runtime allocation allowed) -----
__device__ float g_Q[NN * DIM];
__device__ float g_K[NN * DIM];
__device__ float g_V[NN * DIM];
__device__ float g_E[(size_t)NE * DIM];   // 409.6 MB
__device__ float g_Z[NN * NH];
// Pre-swizzled bf16 weight images (hi / lo split), 4 matrices (q,k,v,e)
__device__ __nv_bfloat16 g_W1img[4][DIM * DIM];
__device__ __nv_bfloat16 g_W2img[4][DIM * DIM];

// ---------------------------------------------------------------------------
__device__ __forceinline__ uint32_t smem_u32(const void* p) {
    uint32_t a;
    asm("{ .reg .u64 t; cvta.to.shared.u64 t, %1; cvt.u32.u64 %0, t; }"
        : "=r"(a) : "l"(p));
    return a;
}

// Swizzled byte offset inside a 128x128 bf16 tile (row-major rows of 256B).
__device__ __forceinline__ uint32_t soff(int r, int k) {
    uint32_t u = (uint32_t)(k >> 3);
    uint32_t us = (u & 8u) | ((u ^ (uint32_t)(r & 7)) & 7u);
    return (uint32_t)r * 256u + us * 16u + (uint32_t)(k & 7) * 2u;
}

__device__ __forceinline__ void ldsm_x4(uint32_t* r, uint32_t addr) {
    asm volatile("ldmatrix.sync.aligned.m8n8.x4.shared.b16 {%0,%1,%2,%3}, [%4];"
                 : "=r"(r[0]), "=r"(r[1]), "=r"(r[2]), "=r"(r[3]) : "r"(addr));
}

__device__ __forceinline__ void mma16816(float* d, const uint32_t* a,
                                         uint32_t b0, uint32_t b1) {
    asm volatile(
        "mma.sync.aligned.m16n8k16.row.col.f32.bf16.bf16.f32 "
        "{%0,%1,%2,%3}, {%4,%5,%6,%7}, {%8,%9}, {%0,%1,%2,%3};"
        : "+f"(d[0]), "+f"(d[1]), "+f"(d[2]), "+f"(d[3])
        : "r"(a[0]), "r"(a[1]), "r"(a[2]), "r"(a[3]), "r"(b0), "r"(b1));
}

__device__ __forceinline__ void cp16(uint32_t dst, const void* src) {
    asm volatile("cp.async.cg.shared.global [%0], [%1], 16;"
                 :: "r"(dst), "l"(src));
}
#define CP_COMMIT() asm volatile("cp.async.commit_group;" ::: "memory")
#define CP_WAIT0()  asm volatile("cp.async.wait_group 0;" ::: "memory")

// ---------------- weight prep: fp32 W[k,n] -> swizzled bf16 hi/lo images -----
__global__ __launch_bounds__(256)
void prep_w_kernel(const float* __restrict__ W0, const float* __restrict__ W1,
                   const float* __restrict__ W2, const float* __restrict__ W3,
                   __nv_bfloat16* __restrict__ img1, __nv_bfloat16* __restrict__ img2) {
    int gi = blockIdx.x * 256 + threadIdx.x;
    if (gi >= 4 * DIM * DIM) return;
    int m = gi >> 14;
    int i = gi & (DIM * DIM - 1);
    const float* W = (m == 0) ? W0 : (m == 1) ? W1 : (m == 2) ? W2 : W3;
    int k = i >> 7;
    int n = i & 127;
    float a = W[i];
    __nv_bfloat16 h = __float2bfloat16(a);
    float lo = a - __bfloat162float(h);
    uint32_t off = soff(n, k);
    *(__nv_bfloat16*)((char*)(img1 + (size_t)m * DIM * DIM) + off) = h;
    *(__nv_bfloat16*)((char*)(img2 + (size_t)m * DIM * DIM) + off) = __float2bfloat16(lo);
}

// ----------- persistent HMMA GEMM: C[M,128] = X[M,128]@W + b ----------------
// smem: bias 1K | A1 32K | A2 32K | W1 32K | W2 32K | STAGE 64K  = 193K
#define SM_BIAS  0
#define SM_A1    1024
#define SM_A2    (1024 + 32768)
#define SM_W1    (1024 + 65536)
#define SM_W2    (1024 + 98304)
#define SM_STAGE (1024 + 131072)
#define SM_TOTAL (1024 + 131072 + 65536)

__global__ __launch_bounds__(256, 1)
void gemm_mma_kernel(const float* __restrict__ X,
                     const __nv_bfloat16* __restrict__ W1img,
                     const __nv_bfloat16* __restrict__ W2img,
                     const float* __restrict__ bias,
                     float* __restrict__ C, int M, int nT) {
    extern __shared__ char smem[];
    const uint32_t sb = smem_u32(smem);
    const int tid = threadIdx.x;
    const int wid = tid >> 5;
    const int lid = tid & 31;

    // ---- one-time: weights + bias into smem ----
    {
        const int4* s1 = (const int4*)W1img;
        const int4* s2 = (const int4*)W2img;
        int4* d1 = (int4*)(smem + SM_W1);
        int4* d2 = (int4*)(smem + SM_W2);
        #pragma unroll
        for (int i = tid; i < 2048; i += 256) {
            d1[i] = s1[i];
            d2[i] = s2[i];
        }
    }
    if (tid < 128) *(float*)(smem + SM_BIAS + tid * 4) = bias[tid];

    // ---- stage-issue helper pattern (16 chunks of 16B per thread) ----
    // chunk j: row = j>>5, c4 = (j&31)*4
    auto issue_tile = [&](int t) {
        const int row0 = t * 128;
        #pragma unroll
        for (int j = tid; j < 4096; j += 256) {
            int r  = j >> 5;
            int c4 = (j & 31) << 2;
            int gr = row0 + r;
            uint32_t dst = sb + SM_STAGE + (uint32_t)j * 16u;
            if (gr < M) {
                cp16(dst, X + (size_t)gr * DIM + c4);
            } else {
                *(int4*)(smem + SM_STAGE + (size_t)j * 16) = make_int4(0, 0, 0, 0);
            }
        }
        CP_COMMIT();
    };

    const int wm = (wid >> 2) * 64;
    const int wn = (wid & 3) * 32;
    const int g  = lid >> 3;
    const int lr = (lid & 7) | ((g & 1) << 3);
    const int kq = (g >> 1) << 3;
    const int cr = lid >> 2;
    const int cc = (lid & 3) * 2;
    const float* sBias = (const float*)(smem + SM_BIAS);

    const uint32_t aoff[3] = { sb + SM_A1, sb + SM_A2, sb + SM_A1 };
    const uint32_t boff[3] = { sb + SM_W1, sb + SM_W1, sb + SM_W2 };

    // prologue: stage first tile
    if ((int)blockIdx.x < nT) issue_tile(blockIdx.x);
    __syncthreads();   // also covers weight/bias loads

    for (int t = blockIdx.x; t < nT; t += gridDim.x) {
        CP_WAIT0();
        __syncthreads();          // stage ready for everyone; prior LDSMs done

        // convert stage -> A1/A2 (hi/lo bf16, swizzled)
        #pragma unroll
        for (int j = tid; j < 4096; j += 256) {
            int r  = j >> 5;
            int k4 = (j & 31) << 2;
            float4 v = *(const float4*)(smem + SM_STAGE + (size_t)j * 16);
            __nv_bfloat16 hx = __float2bfloat16(v.x);
            __nv_bfloat16 hy = __float2bfloat16(v.y);
            __nv_bfloat16 hz = __float2bfloat16(v.z);
            __nv_bfloat16 hw = __float2bfloat16(v.w);
            __nv_bfloat162 hp0; hp0.x = hx; hp0.y = hy;
            __nv_bfloat162 hp1; hp1.x = hz; hp1.y = hw;
            __nv_bfloat162 lp0 = __floats2bfloat162_rn(v.x - __bfloat162float(hx),
                                                       v.y - __bfloat162float(hy));
            __nv_bfloat162 lp1 = __floats2bfloat162_rn(v.z - __bfloat162float(hz),
                                                       v.w - __bfloat162float(hw));
            uint32_t o0 = soff(r, k4);
            *(__nv_bfloat162*)(smem + SM_A1 + o0)     = hp0;
            *(__nv_bfloat162*)(smem + SM_A1 + o0 + 4) = hp1;
            *(__nv_bfloat162*)(smem + SM_A2 + o0)     = lp0;
            *(__nv_bfloat162*)(smem + SM_A2 + o0 + 4) = lp1;
        }
        __syncthreads();          // A1/A2 ready, stage consumed

        // prefetch next tile while MMA runs
        int tn = t + gridDim.x;
        if (tn < nT) issue_tile(tn);

        // ---- MMA: C = A1*W1 + A2*W1 + A1*W2 ----
        float acc[4][4][4];
        #pragma unroll
        for (int i = 0; i < 4; i++)
            #pragma unroll
            for (int j = 0; j < 4; j++)
                #pragma unroll
                for (int u = 0; u < 4; u++) acc[i][j][u] = 0.f;

        #pragma unroll 1
        for (int ph = 0; ph < 3; ph++) {
            const uint32_t ab = aoff[ph];
            const uint32_t bb = boff[ph];
            #pragma unroll
            for (int ks = 0; ks < 8; ks++) {
                const int k0 = ks * 16 + kq;
                uint32_t af[4][4];
                #pragma unroll
                for (int mt = 0; mt < 4; mt++)
                    ldsm_x4(af[mt], ab + soff(wm + mt * 16 + lr, k0));
                uint32_t bf[2][4];
                #pragma unroll
                for (int nt2 = 0; nt2 < 2; nt2++)
                    ldsm_x4(bf[nt2], bb + soff(wn + nt2 * 16 + lr, k0));
                #pragma unroll
                for (int mt = 0; mt < 4; mt++) {
                    mma16816(acc[mt][0], af[mt], bf[0][0], bf[0][2]);
                    mma16816(acc[mt][1], af[mt], bf[0][1], bf[0][3]);
                    mma16816(acc[mt][2], af[mt], bf[1][0], bf[1][2]);
                    mma16816(acc[mt][3], af[mt], bf[1][1], bf[1][3]);
                }
            }
        }

        // epilogue
        const int row0 = t * 128;
        #pragma unroll
        for (int mt = 0; mt < 4; mt++) {
            #pragma unroll
            for (int nt = 0; nt < 4; nt++) {
                int col = wn + nt * 8 + cc;
                float b0 = sBias[col], b1 = sBias[col + 1];
                int r1 = row0 + wm + mt * 16 + cr;
                if (r1 < M) {
                    float2 o; o.x = acc[mt][nt][0] + b0; o.y = acc[mt][nt][1] + b1;
                    *(float2*)(C + (size_t)r1 * DIM + col) = o;
                }
                int r2 = r1 + 8;
                if (r2 < M) {
                    float2 o; o.x = acc[mt][nt][2] + b0; o.y = acc[mt][nt][3] + b1;
                    *(float2*)(C + (size_t)r2 * DIM + col) = o;
                }
            }
        }
        __syncthreads();          // all LDSMs done before next convert
    }
}

// --------------------------- edge scatter kernel ----------------------------
__device__ __forceinline__ void red4(float* p, float a, float b, float c, float d) {
    asm volatile("red.global.add.v4.f32 [%0], {%1, %2, %3, %4};"
                 :: "l"(p), "f"(a), "f"(b), "f"(c), "f"(d) : "memory");
}

__global__ __launch_bounds__(256)
void edge_kernel(const int* __restrict__ ei, const float* __restrict__ E,
                 float* __restrict__ wV, int nE) {
    const int lid   = threadIdx.x & 31;
    const int warp  = (blockIdx.x * blockDim.x + threadIdx.x) >> 5;
    const int nwarp = (gridDim.x * blockDim.x) >> 5;
    const int h  = lid >> 2;
    const int i4 = lid & 3;

    for (int e = warp; e < nE; e += nwarp) {
        int src = __ldg(ei + e);
        int dst = __ldg(ei + nE + e);

        float4 k  = *(const float4*)(g_K + (size_t)src * DIM + 4 * lid);
        float4 q  = *(const float4*)(g_Q + (size_t)dst * DIM + 4 * lid);
        float4 ev = __ldg((const float4*)(E + (size_t)e * DIM + 4 * lid));

        float t = k.x * q.x * ev.x + k.y * q.y * ev.y
                + k.z * q.z * ev.z + k.w * q.w * ev.w;
        t += __shfl_xor_sync(0xFFFFFFFFu, t, 1);
        t += __shfl_xor_sync(0xFFFFFFFFu, t, 2);
        t *= 0.25f;                          // 1/sqrt(16)
        t = fminf(fmaxf(t, -5.f), 5.f);
        float s = __expf(t);

        float4 v = *(const float4*)(g_V + (size_t)src * DIM + 4 * lid);
        red4(wV + (size_t)dst * DIM + 4 * lid, v.x * s, v.y * s, v.z * s, v.w * s);
        if (i4 == 0) atomicAdd(&g_Z[dst * NH + h], s);
    }
}

// ----------------------------- normalize ------------------------------------
__global__ __launch_bounds__(256)
void normalize_kernel(float* __restrict__ out, int n) {
    int i = blockIdx.x * blockDim.x + threadIdx.x;
    if (i >= n) return;
    int node = i >> 7;
    int h    = (i >> 4) & 7;
    float z = g_Z[node * NH + h];
    out[i] = out[i] / (z + 1e-6f);
}

// ----------------------------- launcher -------------------------------------
extern "C" void kernel_launch(void* const* d_in, const int* in_sizes, int n_in,
                              void* d_out, int out_size) {
    const float* x   = (const float*)d_in[0];
    const float* ea  = (const float*)d_in[1];
    const int*   ei  = (const int*)d_in[2];
    const float* Wq  = (const float*)d_in[3];
    const float* bq  = (const float*)d_in[4];
    const float* Wk  = (const float*)d_in[5];
    const float* bk  = (const float*)d_in[6];
    const float* We  = (const float*)d_in[7];
    const float* be  = (const float*)d_in[8];
    const float* Wv  = (const float*)d_in[9];
    const float* bv  = (const float*)d_in[10];
    float* out = (float*)d_out;

    const int nN = in_sizes[0] / DIM;     // 50000
    const int nE = in_sizes[1] / DIM;     // 800000

    float *pQ, *pK, *pV, *pE, *pZ;
    __nv_bfloat16 *pW1, *pW2;
    cudaGetSymbolAddress((void**)&pQ, g_Q);
    cudaGetSymbolAddress((void**)&pK, g_K);
    cudaGetSymbolAddress((void**)&pV, g_V);
    cudaGetSymbolAddress((void**)&pE, g_E);
    cudaGetSymbolAddress((void**)&pZ, g_Z);
    cudaGetSymbolAddress((void**)&pW1, g_W1img);
    cudaGetSymbolAddress((void**)&pW2, g_W2img);

    cudaMemsetAsync(d_out, 0, (size_t)out_size * sizeof(float));
    cudaMemsetAsync(pZ, 0, (size_t)nN * NH * sizeof(float));

    prep_w_kernel<<<(4 * DIM * DIM + 255) / 256, 256>>>(Wq, Wk, Wv, We, pW1, pW2);

    cudaFuncSetAttribute(gemm_mma_kernel, cudaFuncAttributeMaxDynamicSharedMemorySize, SM_TOTAL);

    int tN = (nN + 127) / 128;    // 391
    int tE = (nE + 127) / 128;    // 6250
    int gN = tN < 148 ? tN : 148;
    gemm_mma_kernel<<<gN, 256, SM_TOTAL>>>(x,  pW1 + 0 * DIM * DIM, pW2 + 0 * DIM * DIM, bq, pQ, nN, tN);
    gemm_mma_kernel<<<gN, 256, SM_TOTAL>>>(x,  pW1 + 1 * DIM * DIM, pW2 + 1 * DIM * DIM, bk, pK, nN, tN);
    gemm_mma_kernel<<<gN, 256, SM_TOTAL>>>(x,  pW1 + 2 * DIM * DIM, pW2 + 2 * DIM * DIM, bv, pV, nN, tN);
    gemm_mma_kernel<<<148, 256, SM_TOTAL>>>(ea, pW1 + 3 * DIM * DIM, pW2 + 3 * DIM * DIM, be, pE, nE, tE);

    edge_kernel<<<4096, 256>>>(ei, pE, out, nE);

    int totalO = nN * DIM;
    normalize_kernel<<<(totalO + 255) / 256, 256>>>(out, totalO);
}

// round 6
// speedup vs baseline: 2.7899x; 1.0587x over previous
#include <cuda_runtime.h>
#include <cuda_bf16.h>
#include <math.h>
#include <stdint.h>

// Problem constants (shape-fixed per reference)
#define NN   50000
#define NE   800000
#define DIM  128
#define NH   8
#define HD   16

// -------- scratch in __device__ globals (no runtime allocation allowed) -----
__device__ float g_Q[NN * DIM];
__device__ float g_K[NN * DIM];
__device__ float g_V[NN * DIM];
__device__ float g_E[(size_t)NE * DIM];   // 409.6 MB
__device__ float g_Z[NN * NH];
// Pre-swizzled bf16 weight images (hi / lo split), 4 matrices (q,k,v,e)
__device__ __nv_bfloat16 g_W1img[4][DIM * DIM];
__device__ __nv_bfloat16 g_W2img[4][DIM * DIM];

// ---------------------------------------------------------------------------
__device__ __forceinline__ uint32_t smem_u32(const void* p) {
    uint32_t a;
    asm("{ .reg .u64 t; cvta.to.shared.u64 t, %1; cvt.u32.u64 %0, t; }"
        : "=r"(a) : "l"(p));
    return a;
}

// Swizzled byte offset inside a 128x128 bf16 tile (row-major rows of 256B).
__device__ __forceinline__ uint32_t soff(int r, int k) {
    uint32_t u = (uint32_t)(k >> 3);
    uint32_t us = (u & 8u) | ((u ^ (uint32_t)(r & 7)) & 7u);
    return (uint32_t)r * 256u + us * 16u + (uint32_t)(k & 7) * 2u;
}

__device__ __forceinline__ void ldsm_x4(uint32_t* r, uint32_t addr) {
    asm volatile("ldmatrix.sync.aligned.m8n8.x4.shared.b16 {%0,%1,%2,%3}, [%4];"
                 : "=r"(r[0]), "=r"(r[1]), "=r"(r[2]), "=r"(r[3]) : "r"(addr));
}

__device__ __forceinline__ void mma16816(float* d, const uint32_t* a,
                                         uint32_t b0, uint32_t b1) {
    asm volatile(
        "mma.sync.aligned.m16n8k16.row.col.f32.bf16.bf16.f32 "
        "{%0,%1,%2,%3}, {%4,%5,%6,%7}, {%8,%9}, {%0,%1,%2,%3};"
        : "+f"(d[0]), "+f"(d[1]), "+f"(d[2]), "+f"(d[3])
        : "r"(a[0]), "r"(a[1]), "r"(a[2]), "r"(a[3]), "r"(b0), "r"(b1));
}

__device__ __forceinline__ void cp16(uint32_t dst, const void* src) {
    asm volatile("cp.async.cg.shared.global [%0], [%1], 16;"
                 :: "r"(dst), "l"(src));
}
#define CP_COMMIT() asm volatile("cp.async.commit_group;" ::: "memory")
#define CP_WAIT0()  asm volatile("cp.async.wait_group 0;" ::: "memory")

// ---------------- weight prep: fp32 W[k,n] -> swizzled bf16 hi/lo images -----
__global__ __launch_bounds__(256)
void prep_w_kernel(const float* __restrict__ W0, const float* __restrict__ W1,
                   const float* __restrict__ W2, const float* __restrict__ W3,
                   __nv_bfloat16* __restrict__ img1, __nv_bfloat16* __restrict__ img2) {
    int gi = blockIdx.x * 256 + threadIdx.x;
    if (gi >= 4 * DIM * DIM) return;
    int m = gi >> 14;
    int i = gi & (DIM * DIM - 1);
    const float* W = (m == 0) ? W0 : (m == 1) ? W1 : (m == 2) ? W2 : W3;
    int k = i >> 7;
    int n = i & 127;
    float a = W[i];
    __nv_bfloat16 h = __float2bfloat16(a);
    float lo = a - __bfloat162float(h);
    uint32_t off = soff(n, k);
    *(__nv_bfloat16*)((char*)(img1 + (size_t)m * DIM * DIM) + off) = h;
    *(__nv_bfloat16*)((char*)(img2 + (size_t)m * DIM * DIM) + off) = __float2bfloat16(lo);
}

// ----------- persistent HMMA GEMM: C[M,128] = X[M,128]@W + b ----------------
// 512 threads, 16 warps in 4(M)x4(N) grid, 32x32 warp tiles.
// smem: bias 1K | A1 32K | A2 32K | W1 32K | W2 32K | STAGE 64K  = 193K
#define SM_BIAS  0
#define SM_A1    1024
#define SM_A2    (1024 + 32768)
#define SM_W1    (1024 + 65536)
#define SM_W2    (1024 + 98304)
#define SM_STAGE (1024 + 131072)
#define SM_TOTAL (1024 + 131072 + 65536)
#define GTHREADS 512

__global__ __launch_bounds__(GTHREADS, 1)
void gemm_mma_kernel(const float* __restrict__ X,
                     const __nv_bfloat16* __restrict__ W1img,
                     const __nv_bfloat16* __restrict__ W2img,
                     const float* __restrict__ bias,
                     float* __restrict__ C, int M, int nT) {
    extern __shared__ char smem[];
    const uint32_t sb = smem_u32(smem);
    const int tid = threadIdx.x;
    const int wid = tid >> 5;
    const int lid = tid & 31;

    // ---- one-time: weights + bias into smem ----
    {
        const int4* s1 = (const int4*)W1img;
        const int4* s2 = (const int4*)W2img;
        int4* d1 = (int4*)(smem + SM_W1);
        int4* d2 = (int4*)(smem + SM_W2);
        #pragma unroll
        for (int i = tid; i < 2048; i += GTHREADS) {
            d1[i] = s1[i];
            d2[i] = s2[i];
        }
    }
    if (tid < 128) *(float*)(smem + SM_BIAS + tid * 4) = bias[tid];

    auto issue_tile = [&](int t) {
        const int row0 = t * 128;
        #pragma unroll
        for (int j = tid; j < 4096; j += GTHREADS) {
            int r  = j >> 5;
            int c4 = (j & 31) << 2;
            int gr = row0 + r;
            uint32_t dst = sb + SM_STAGE + (uint32_t)j * 16u;
            if (gr < M) {
                cp16(dst, X + (size_t)gr * DIM + c4);
            } else {
                *(int4*)(smem + SM_STAGE + (size_t)j * 16) = make_int4(0, 0, 0, 0);
            }
        }
        CP_COMMIT();
    };

    const int wm = (wid >> 2) * 32;   // 0,32,64,96
    const int wn = (wid & 3) * 32;    // 0,32,64,96
    const int g  = lid >> 3;
    const int lr = (lid & 7) | ((g & 1) << 3);
    const int kq = (g >> 1) << 3;
    const int cr = lid >> 2;
    const int cc = (lid & 3) * 2;
    const float* sBias = (const float*)(smem + SM_BIAS);

    const uint32_t aoff[3] = { sb + SM_A1, sb + SM_A2, sb + SM_A1 };
    const uint32_t boff[3] = { sb + SM_W1, sb + SM_W1, sb + SM_W2 };

    if ((int)blockIdx.x < nT) issue_tile(blockIdx.x);
    __syncthreads();

    for (int t = blockIdx.x; t < nT; t += gridDim.x) {
        CP_WAIT0();
        __syncthreads();

        // convert stage -> A1/A2 (hi/lo bf16, swizzled): 8 iters/thread
        #pragma unroll
        for (int j = tid; j < 4096; j += GTHREADS) {
            int r  = j >> 5;
            int k4 = (j & 31) << 2;
            float4 v = *(const float4*)(smem + SM_STAGE + (size_t)j * 16);
            __nv_bfloat16 hx = __float2bfloat16(v.x);
            __nv_bfloat16 hy = __float2bfloat16(v.y);
            __nv_bfloat16 hz = __float2bfloat16(v.z);
            __nv_bfloat16 hw = __float2bfloat16(v.w);
            __nv_bfloat162 hp0; hp0.x = hx; hp0.y = hy;
            __nv_bfloat162 hp1; hp1.x = hz; hp1.y = hw;
            __nv_bfloat162 lp0 = __floats2bfloat162_rn(v.x - __bfloat162float(hx),
                                                       v.y - __bfloat162float(hy));
            __nv_bfloat162 lp1 = __floats2bfloat162_rn(v.z - __bfloat162float(hz),
                                                       v.w - __bfloat162float(hw));
            uint32_t o0 = soff(r, k4);
            *(__nv_bfloat162*)(smem + SM_A1 + o0)     = hp0;
            *(__nv_bfloat162*)(smem + SM_A1 + o0 + 4) = hp1;
            *(__nv_bfloat162*)(smem + SM_A2 + o0)     = lp0;
            *(__nv_bfloat162*)(smem + SM_A2 + o0 + 4) = lp1;
        }
        __syncthreads();

        // prefetch next tile while MMA runs
        int tn = t + gridDim.x;
        if (tn < nT) issue_tile(tn);

        // ---- MMA: C = A1*W1 + A2*W1 + A1*W2 ----
        float acc[2][4][4];
        #pragma unroll
        for (int i = 0; i < 2; i++)
            #pragma unroll
            for (int j = 0; j < 4; j++)
                #pragma unroll
                for (int u = 0; u < 4; u++) acc[i][j][u] = 0.f;

        #pragma unroll 1
        for (int ph = 0; ph < 3; ph++) {
            const uint32_t ab = aoff[ph];
            const uint32_t bb = boff[ph];
            #pragma unroll
            for (int ks = 0; ks < 8; ks++) {
                const int k0 = ks * 16 + kq;
                uint32_t af[2][4];
                #pragma unroll
                for (int mt = 0; mt < 2; mt++)
                    ldsm_x4(af[mt], ab + soff(wm + mt * 16 + lr, k0));
                uint32_t bf[2][4];
                #pragma unroll
                for (int nt2 = 0; nt2 < 2; nt2++)
                    ldsm_x4(bf[nt2], bb + soff(wn + nt2 * 16 + lr, k0));
                #pragma unroll
                for (int mt = 0; mt < 2; mt++) {
                    mma16816(acc[mt][0], af[mt], bf[0][0], bf[0][2]);
                    mma16816(acc[mt][1], af[mt], bf[0][1], bf[0][3]);
                    mma16816(acc[mt][2], af[mt], bf[1][0], bf[1][2]);
                    mma16816(acc[mt][3], af[mt], bf[1][1], bf[1][3]);
                }
            }
        }

        // epilogue
        const int row0 = t * 128;
        #pragma unroll
        for (int mt = 0; mt < 2; mt++) {
            #pragma unroll
            for (int nt = 0; nt < 4; nt++) {
                int col = wn + nt * 8 + cc;
                float b0 = sBias[col], b1 = sBias[col + 1];
                int r1 = row0 + wm + mt * 16 + cr;
                if (r1 < M) {
                    float2 o; o.x = acc[mt][nt][0] + b0; o.y = acc[mt][nt][1] + b1;
                    *(float2*)(C + (size_t)r1 * DIM + col) = o;
                }
                int r2 = r1 + 8;
                if (r2 < M) {
                    float2 o; o.x = acc[mt][nt][2] + b0; o.y = acc[mt][nt][3] + b1;
                    *(float2*)(C + (size_t)r2 * DIM + col) = o;
                }
            }
        }
        __syncthreads();
    }
}

// --------------------------- edge scatter kernel ----------------------------
__device__ __forceinline__ void red4(float* p, float a, float b, float c, float d) {
    asm volatile("red.global.add.v4.f32 [%0], {%1, %2, %3, %4};"
                 :: "l"(p), "f"(a), "f"(b), "f"(c), "f"(d) : "memory");
}

__global__ __launch_bounds__(256)
void edge_kernel(const int* __restrict__ ei, const float* __restrict__ E,
                 float* __restrict__ wV, int nE) {
    const int lid   = threadIdx.x & 31;
    const int warp  = (blockIdx.x * blockDim.x + threadIdx.x) >> 5;
    const int nwarp = (gridDim.x * blockDim.x) >> 5;
    const int h  = lid >> 2;
    const int i4 = lid & 3;

    for (int e = warp; e < nE; e += nwarp) {
        int src = __ldg(ei + e);
        int dst = __ldg(ei + nE + e);

        float4 k  = *(const float4*)(g_K + (size_t)src * DIM + 4 * lid);
        float4 q  = *(const float4*)(g_Q + (size_t)dst * DIM + 4 * lid);
        float4 ev = __ldg((const float4*)(E + (size_t)e * DIM + 4 * lid));

        float t = k.x * q.x * ev.x + k.y * q.y * ev.y
                + k.z * q.z * ev.z + k.w * q.w * ev.w;
        t += __shfl_xor_sync(0xFFFFFFFFu, t, 1);
        t += __shfl_xor_sync(0xFFFFFFFFu, t, 2);
        t *= 0.25f;                          // 1/sqrt(16)
        t = fminf(fmaxf(t, -5.f), 5.f);
        float s = __expf(t);

        float4 v = *(const float4*)(g_V + (size_t)src * DIM + 4 * lid);
        red4(wV + (size_t)dst * DIM + 4 * lid, v.x * s, v.y * s, v.z * s, v.w * s);
        if (i4 == 0) atomicAdd(&g_Z[dst * NH + h], s);
    }
}

// ----------------------------- normalize ------------------------------------
__global__ __launch_bounds__(256)
void normalize_kernel(float* __restrict__ out, int n) {
    int i = blockIdx.x * blockDim.x + threadIdx.x;
    if (i >= n) return;
    int node = i >> 7;
    int h    = (i >> 4) & 7;
    float z = g_Z[node * NH + h];
    out[i] = out[i] / (z + 1e-6f);
}

// ----------------------------- launcher -------------------------------------
extern "C" void kernel_launch(void* const* d_in, const int* in_sizes, int n_in,
                              void* d_out, int out_size) {
    const float* x   = (const float*)d_in[0];
    const float* ea  = (const float*)d_in[1];
    const int*   ei  = (const int*)d_in[2];
    const float* Wq  = (const float*)d_in[3];
    const float* bq  = (const float*)d_in[4];
    const float* Wk  = (const float*)d_in[5];
    const float* bk  = (const float*)d_in[6];
    const float* We  = (const float*)d_in[7];
    const float* be  = (const float*)d_in[8];
    const float* Wv  = (const float*)d_in[9];
    const float* bv  = (const float*)d_in[10];
    float* out = (float*)d_out;

    const int nN = in_sizes[0] / DIM;     // 50000
    const int nE = in_sizes[1] / DIM;     // 800000

    float *pQ, *pK, *pV, *pE, *pZ;
    __nv_bfloat16 *pW1, *pW2;
    cudaGetSymbolAddress((void**)&pQ, g_Q);
    cudaGetSymbolAddress((void**)&pK, g_K);
    cudaGetSymbolAddress((void**)&pV, g_V);
    cudaGetSymbolAddress((void**)&pE, g_E);
    cudaGetSymbolAddress((void**)&pZ, g_Z);
    cudaGetSymbolAddress((void**)&pW1, g_W1img);
    cudaGetSymbolAddress((void**)&pW2, g_W2img);

    cudaMemsetAsync(d_out, 0, (size_t)out_size * sizeof(float));
    cudaMemsetAsync(pZ, 0, (size_t)nN * NH * sizeof(float));

    prep_w_kernel<<<(4 * DIM * DIM + 255) / 256, 256>>>(Wq, Wk, Wv, We, pW1, pW2);

    cudaFuncSetAttribute(gemm_mma_kernel, cudaFuncAttributeMaxDynamicSharedMemorySize, SM_TOTAL);

    int tN = (nN + 127) / 128;    // 391
    int tE = (nE + 127) / 128;    // 6250
    int gN = tN < 148 ? tN : 148;
    gemm_mma_kernel<<<gN, GTHREADS, SM_TOTAL>>>(x,  pW1 + 0 * DIM * DIM, pW2 + 0 * DIM * DIM, bq, pQ, nN, tN);
    gemm_mma_kernel<<<gN, GTHREADS, SM_TOTAL>>>(x,  pW1 + 1 * DIM * DIM, pW2 + 1 * DIM * DIM, bk, pK, nN, tN);
    gemm_mma_kernel<<<gN, GTHREADS, SM_TOTAL>>>(x,  pW1 + 2 * DIM * DIM, pW2 + 2 * DIM * DIM, bv, pV, nN, tN);
    gemm_mma_kernel<<<148, GTHREADS, SM_TOTAL>>>(ea, pW1 + 3 * DIM * DIM, pW2 + 3 * DIM * DIM, be, pE, nE, tE);

    edge_kernel<<<4096, 256>>>(ei, pE, out, nE);

    int totalO = nN * DIM;
    normalize_kernel<<<(totalO + 255) / 256, 256>>>(out, totalO);
}

// round 7
// speedup vs baseline: 2.8873x; 1.0349x over previous
#include <cuda_runtime.h>
#include <cuda_bf16.h>
#include <math.h>
#include <stdint.h>

// Problem constants (shape-fixed per reference)
#define NN   50000
#define NE   800000
#define DIM  128
#define NH   8
#define HD   16

// -------- scratch in __device__ globals (no runtime allocation allowed) -----
__device__ float g_Q[NN * DIM];
__device__ float g_K[NN * DIM];
__device__ float g_V[NN * DIM];
__device__ float g_E[(size_t)NE * DIM];   // 409.6 MB
__device__ float g_Z[NN * NH];
// Pre-swizzled bf16 weight images (hi / lo split), 4 matrices (q,k,v,e)
__device__ __nv_bfloat16 g_W1img[4][DIM * DIM];
__device__ __nv_bfloat16 g_W2img[4][DIM * DIM];

// ---------------------------------------------------------------------------
__device__ __forceinline__ uint32_t smem_u32(const void* p) {
    uint32_t a;
    asm("{ .reg .u64 t; cvta.to.shared.u64 t, %1; cvt.u32.u64 %0, t; }"
        : "=r"(a) : "l"(p));
    return a;
}

// Swizzled byte offset inside a 128x128 bf16 tile (row-major rows of 256B).
__device__ __forceinline__ uint32_t soff(int r, int k) {
    uint32_t u = (uint32_t)(k >> 3);
    uint32_t us = (u & 8u) | ((u ^ (uint32_t)(r & 7)) & 7u);
    return (uint32_t)r * 256u + us * 16u + (uint32_t)(k & 7) * 2u;
}

// Non-volatile (schedulable) ldmatrix with memory clobber: ordered vs
// barriers/STS, but HMMAs (pure register asm) can interleave around it.
__device__ __forceinline__ void ldsm_x4(uint32_t* r, uint32_t addr) {
    asm("ldmatrix.sync.aligned.m8n8.x4.shared.b16 {%0,%1,%2,%3}, [%4];"
        : "=r"(r[0]), "=r"(r[1]), "=r"(r[2]), "=r"(r[3]) : "r"(addr) : "memory");
}

__device__ __forceinline__ void mma16816(float* d, const uint32_t* a,
                                         uint32_t b0, uint32_t b1) {
    asm("mma.sync.aligned.m16n8k16.row.col.f32.bf16.bf16.f32 "
        "{%0,%1,%2,%3}, {%4,%5,%6,%7}, {%8,%9}, {%0,%1,%2,%3};"
        : "+f"(d[0]), "+f"(d[1]), "+f"(d[2]), "+f"(d[3])
        : "r"(a[0]), "r"(a[1]), "r"(a[2]), "r"(a[3]), "r"(b0), "r"(b1));
}

__device__ __forceinline__ void cp16(uint32_t dst, const void* src) {
    asm volatile("cp.async.cg.shared.global [%0], [%1], 16;"
                 :: "r"(dst), "l"(src));
}
#define CP_COMMIT() asm volatile("cp.async.commit_group;" ::: "memory")
#define CP_WAIT0()  asm volatile("cp.async.wait_group 0;" ::: "memory")

// ---------------- weight prep: fp32 W[k,n] -> swizzled bf16 hi/lo images -----
__global__ __launch_bounds__(256)
void prep_w_kernel(const float* __restrict__ W0, const float* __restrict__ W1,
                   const float* __restrict__ W2, const float* __restrict__ W3,
                   __nv_bfloat16* __restrict__ img1, __nv_bfloat16* __restrict__ img2) {
    int gi = blockIdx.x * 256 + threadIdx.x;
    if (gi >= 4 * DIM * DIM) return;
    int m = gi >> 14;
    int i = gi & (DIM * DIM - 1);
    const float* W = (m == 0) ? W0 : (m == 1) ? W1 : (m == 2) ? W2 : W3;
    int k = i >> 7;
    int n = i & 127;
    float a = W[i];
    __nv_bfloat16 h = __float2bfloat16(a);
    float lo = a - __bfloat162float(h);
    uint32_t off = soff(n, k);
    *(__nv_bfloat16*)((char*)(img1 + (size_t)m * DIM * DIM) + off) = h;
    *(__nv_bfloat16*)((char*)(img2 + (size_t)m * DIM * DIM) + off) = __float2bfloat16(lo);
}

// ----------- persistent HMMA GEMM: C[M,128] = X[M,128]@W + b ----------------
// 512 threads, 16 warps in 4(M)x4(N) grid, 32x32 warp tiles.
// smem: bias 1K | A1 32K | A2 32K | W1 32K | W2 32K | STAGE 64K  = 193K
#define SM_BIAS  0
#define SM_A1    1024
#define SM_A2    (1024 + 32768)
#define SM_W1    (1024 + 65536)
#define SM_W2    (1024 + 98304)
#define SM_STAGE (1024 + 131072)
#define SM_TOTAL (1024 + 131072 + 65536)
#define GTHREADS 512

__global__ __launch_bounds__(GTHREADS, 1)
void gemm_mma_kernel(const float* __restrict__ X,
                     const __nv_bfloat16* __restrict__ W1img,
                     const __nv_bfloat16* __restrict__ W2img,
                     const float* __restrict__ bias,
                     float* __restrict__ C, int M, int nT) {
    extern __shared__ char smem[];
    const uint32_t sb = smem_u32(smem);
    const int tid = threadIdx.x;
    const int wid = tid >> 5;
    const int lid = tid & 31;

    // ---- one-time: weights + bias into smem ----
    {
        const int4* s1 = (const int4*)W1img;
        const int4* s2 = (const int4*)W2img;
        int4* d1 = (int4*)(smem + SM_W1);
        int4* d2 = (int4*)(smem + SM_W2);
        #pragma unroll
        for (int i = tid; i < 2048; i += GTHREADS) {
            d1[i] = s1[i];
            d2[i] = s2[i];
        }
    }
    if (tid < 128) *(float*)(smem + SM_BIAS + tid * 4) = bias[tid];

    auto issue_tile = [&](int t) {
        const int row0 = t * 128;
        #pragma unroll
        for (int j = tid; j < 4096; j += GTHREADS) {
            int r  = j >> 5;
            int c4 = (j & 31) << 2;
            int gr = row0 + r;
            uint32_t dst = sb + SM_STAGE + (uint32_t)j * 16u;
            if (gr < M) {
                cp16(dst, X + (size_t)gr * DIM + c4);
            } else {
                *(int4*)(smem + SM_STAGE + (size_t)j * 16) = make_int4(0, 0, 0, 0);
            }
        }
        CP_COMMIT();
    };

    const int wm = (wid >> 2) * 32;   // 0,32,64,96
    const int wn = (wid & 3) * 32;    // 0,32,64,96
    const int g  = lid >> 3;
    const int lr = (lid & 7) | ((g & 1) << 3);
    const int kq = (g >> 1) << 3;
    const int cr = lid >> 2;
    const int cc = (lid & 3) * 2;
    const float* sBias = (const float*)(smem + SM_BIAS);

    if ((int)blockIdx.x < nT) issue_tile(blockIdx.x);
    __syncthreads();

    for (int t = blockIdx.x; t < nT; t += gridDim.x) {
        CP_WAIT0();
        __syncthreads();

        // convert stage -> A1/A2 (hi/lo bf16, swizzled): 8 iters/thread
        #pragma unroll
        for (int j = tid; j < 4096; j += GTHREADS) {
            int r  = j >> 5;
            int k4 = (j & 31) << 2;
            float4 v = *(const float4*)(smem + SM_STAGE + (size_t)j * 16);
            __nv_bfloat162 hp0 = __floats2bfloat162_rn(v.x, v.y);
            __nv_bfloat162 hp1 = __floats2bfloat162_rn(v.z, v.w);
            __nv_bfloat162 lp0 = __floats2bfloat162_rn(v.x - __bfloat162float(hp0.x),
                                                       v.y - __bfloat162float(hp0.y));
            __nv_bfloat162 lp1 = __floats2bfloat162_rn(v.z - __bfloat162float(hp1.x),
                                                       v.w - __bfloat162float(hp1.y));
            uint32_t o0 = soff(r, k4);           // 8B-aligned (k4 % 8 ∈ {0,4})
            uint2 hq, lq;
            hq.x = *(uint32_t*)&hp0; hq.y = *(uint32_t*)&hp1;
            lq.x = *(uint32_t*)&lp0; lq.y = *(uint32_t*)&lp1;
            *(uint2*)(smem + SM_A1 + o0) = hq;
            *(uint2*)(smem + SM_A2 + o0) = lq;
        }
        __syncthreads();

        // prefetch next tile while MMA runs
        int tn = t + gridDim.x;
        if (tn < nT) issue_tile(tn);

        // ---- MMA: C = A1*W1 + A2*W1 + A1*W2, single fused k-loop ----
        float acc[2][4][4];
        #pragma unroll
        for (int i = 0; i < 2; i++)
            #pragma unroll
            for (int j = 0; j < 4; j++)
                #pragma unroll
                for (int u = 0; u < 4; u++) acc[i][j][u] = 0.f;

        #pragma unroll
        for (int ks = 0; ks < 8; ks++) {
            const int k0 = ks * 16 + kq;
            uint32_t a1f[2][4], a2f[2][4], b1f[2][4], b2f[2][4];
            #pragma unroll
            for (int mt = 0; mt < 2; mt++) {
                ldsm_x4(a1f[mt], sb + SM_A1 + soff(wm + mt * 16 + lr, k0));
                ldsm_x4(a2f[mt], sb + SM_A2 + soff(wm + mt * 16 + lr, k0));
            }
            #pragma unroll
            for (int nt2 = 0; nt2 < 2; nt2++) {
                ldsm_x4(b1f[nt2], sb + SM_W1 + soff(wn + nt2 * 16 + lr, k0));
                ldsm_x4(b2f[nt2], sb + SM_W2 + soff(wn + nt2 * 16 + lr, k0));
            }
            #pragma unroll
            for (int mt = 0; mt < 2; mt++) {
                // A1 * W1
                mma16816(acc[mt][0], a1f[mt], b1f[0][0], b1f[0][2]);
                mma16816(acc[mt][1], a1f[mt], b1f[0][1], b1f[0][3]);
                mma16816(acc[mt][2], a1f[mt], b1f[1][0], b1f[1][2]);
                mma16816(acc[mt][3], a1f[mt], b1f[1][1], b1f[1][3]);
                // A2 * W1
                mma16816(acc[mt][0], a2f[mt], b1f[0][0], b1f[0][2]);
                mma16816(acc[mt][1], a2f[mt], b1f[0][1], b1f[0][3]);
                mma16816(acc[mt][2], a2f[mt], b1f[1][0], b1f[1][2]);
                mma16816(acc[mt][3], a2f[mt], b1f[1][1], b1f[1][3]);
                // A1 * W2
                mma16816(acc[mt][0], a1f[mt], b2f[0][0], b2f[0][2]);
                mma16816(acc[mt][1], a1f[mt], b2f[0][1], b2f[0][3]);
                mma16816(acc[mt][2], a1f[mt], b2f[1][0], b2f[1][2]);
                mma16816(acc[mt][3], a1f[mt], b2f[1][1], b2f[1][3]);
            }
        }

        // epilogue
        const int row0 = t * 128;
        #pragma unroll
        for (int mt = 0; mt < 2; mt++) {
            #pragma unroll
            for (int nt = 0; nt < 4; nt++) {
                int col = wn + nt * 8 + cc;
                float b0 = sBias[col], b1 = sBias[col + 1];
                int r1 = row0 + wm + mt * 16 + cr;
                if (r1 < M) {
                    float2 o; o.x = acc[mt][nt][0] + b0; o.y = acc[mt][nt][1] + b1;
                    *(float2*)(C + (size_t)r1 * DIM + col) = o;
                }
                int r2 = r1 + 8;
                if (r2 < M) {
                    float2 o; o.x = acc[mt][nt][2] + b0; o.y = acc[mt][nt][3] + b1;
                    *(float2*)(C + (size_t)r2 * DIM + col) = o;
                }
            }
        }
        __syncthreads();
    }
}

// --------------------------- edge scatter kernel ----------------------------
__device__ __forceinline__ void red4(float* p, float a, float b, float c, float d) {
    asm volatile("red.global.add.v4.f32 [%0], {%1, %2, %3, %4};"
                 :: "l"(p), "f"(a), "f"(b), "f"(c), "f"(d) : "memory");
}

__global__ __launch_bounds__(256)
void edge_kernel(const int* __restrict__ ei, const float* __restrict__ E,
                 float* __restrict__ wV, int nE) {
    const int lid   = threadIdx.x & 31;
    const int warp  = (blockIdx.x * blockDim.x + threadIdx.x) >> 5;
    const int nwarp = (gridDim.x * blockDim.x) >> 5;
    const int h  = lid >> 2;
    const int i4 = lid & 3;

    for (int e = warp; e < nE; e += nwarp) {
        int src = __ldg(ei + e);
        int dst = __ldg(ei + nE + e);

        float4 k  = *(const float4*)(g_K + (size_t)src * DIM + 4 * lid);
        float4 q  = *(const float4*)(g_Q + (size_t)dst * DIM + 4 * lid);
        float4 ev = __ldg((const float4*)(E + (size_t)e * DIM + 4 * lid));

        float t = k.x * q.x * ev.x + k.y * q.y * ev.y
                + k.z * q.z * ev.z + k.w * q.w * ev.w;
        t += __shfl_xor_sync(0xFFFFFFFFu, t, 1);
        t += __shfl_xor_sync(0xFFFFFFFFu, t, 2);
        t *= 0.25f;                          // 1/sqrt(16)
        t = fminf(fmaxf(t, -5.f), 5.f);
        float s = __expf(t);

        float4 v = *(const float4*)(g_V + (size_t)src * DIM + 4 * lid);
        red4(wV + (size_t)dst * DIM + 4 * lid, v.x * s, v.y * s, v.z * s, v.w * s);
        if (i4 == 0) atomicAdd(&g_Z[dst * NH + h], s);
    }
}

// ----------------------------- normalize ------------------------------------
__global__ __launch_bounds__(256)
void normalize_kernel(float* __restrict__ out, int n) {
    int i = blockIdx.x * blockDim.x + threadIdx.x;
    if (i >= n) return;
    int node = i >> 7;
    int h    = (i >> 4) & 7;
    float z = g_Z[node * NH + h];
    out[i] = out[i] / (z + 1e-6f);
}

// ----------------------------- launcher -------------------------------------
extern "C" void kernel_launch(void* const* d_in, const int* in_sizes, int n_in,
                              void* d_out, int out_size) {
    const float* x   = (const float*)d_in[0];
    const float* ea  = (const float*)d_in[1];
    const int*   ei  = (const int*)d_in[2];
    const float* Wq  = (const float*)d_in[3];
    const float* bq  = (const float*)d_in[4];
    const float* Wk  = (const float*)d_in[5];
    const float* bk  = (const float*)d_in[6];
    const float* We  = (const float*)d_in[7];
    const float* be  = (const float*)d_in[8];
    const float* Wv  = (const float*)d_in[9];
    const float* bv  = (const float*)d_in[10];
    float* out = (float*)d_out;

    const int nN = in_sizes[0] / DIM;     // 50000
    const int nE = in_sizes[1] / DIM;     // 800000

    float *pQ, *pK, *pV, *pE, *pZ;
    __nv_bfloat16 *pW1, *pW2;
    cudaGetSymbolAddress((void**)&pQ, g_Q);
    cudaGetSymbolAddress((void**)&pK, g_K);
    cudaGetSymbolAddress((void**)&pV, g_V);
    cudaGetSymbolAddress((void**)&pE, g_E);
    cudaGetSymbolAddress((void**)&pZ, g_Z);
    cudaGetSymbolAddress((void**)&pW1, g_W1img);
    cudaGetSymbolAddress((void**)&pW2, g_W2img);

    cudaMemsetAsync(d_out, 0, (size_t)out_size * sizeof(float));
    cudaMemsetAsync(pZ, 0, (size_t)nN * NH * sizeof(float));

    prep_w_kernel<<<(4 * DIM * DIM + 255) / 256, 256>>>(Wq, Wk, Wv, We, pW1, pW2);

    cudaFuncSetAttribute(gemm_mma_kernel, cudaFuncAttributeMaxDynamicSharedMemorySize, SM_TOTAL);

    int tN = (nN + 127) / 128;    // 391
    int tE = (nE + 127) / 128;    // 6250
    int gN = tN < 148 ? tN : 148;
    gemm_mma_kernel<<<gN, GTHREADS, SM_TOTAL>>>(x,  pW1 + 0 * DIM * DIM, pW2 + 0 * DIM * DIM, bq, pQ, nN, tN);
    gemm_mma_kernel<<<gN, GTHREADS, SM_TOTAL>>>(x,  pW1 + 1 * DIM * DIM, pW2 + 1 * DIM * DIM, bk, pK, nN, tN);
    gemm_mma_kernel<<<gN, GTHREADS, SM_TOTAL>>>(x,  pW1 + 2 * DIM * DIM, pW2 + 2 * DIM * DIM, bv, pV, nN, tN);
    gemm_mma_kernel<<<148, GTHREADS, SM_TOTAL>>>(ea, pW1 + 3 * DIM * DIM, pW2 + 3 * DIM * DIM, be, pE, nE, tE);

    edge_kernel<<<4096, 256>>>(ei, pE, out, nE);

    int totalO = nN * DIM;
    normalize_kernel<<<(totalO + 255) / 256, 256>>>(out, totalO);
}

// round 8
// speedup vs baseline: 3.0314x; 1.0499x over previous
#include <cuda_runtime.h>
#include <cuda_bf16.h>
#include <math.h>
#include <stdint.h>

// Problem constants (shape-fixed per reference)
#define NN   50000
#define NE   800000
#define DIM  128
#define NH   8
#define HD   16

// -------- scratch in __device__ globals (no runtime allocation allowed) -----
__device__ float g_Q[NN * DIM];
__device__ float g_K[NN * DIM];
__device__ float g_V[NN * DIM];
__device__ float g_E[(size_t)NE * DIM];   // 409.6 MB
__device__ float g_Z[NN * NH];
// Pre-swizzled bf16 weight images (hi / lo split), 4 matrices (q,k,v,e)
__device__ __nv_bfloat16 g_W1img[4][DIM * DIM];
__device__ __nv_bfloat16 g_W2img[4][DIM * DIM];

// ---------------------------------------------------------------------------
__device__ __forceinline__ uint32_t smem_u32(const void* p) {
    uint32_t a;
    asm("{ .reg .u64 t; cvta.to.shared.u64 t, %1; cvt.u32.u64 %0, t; }"
        : "=r"(a) : "l"(p));
    return a;
}

// Swizzled byte offset inside a 128x128 bf16 tile (row-major rows of 256B).
__device__ __forceinline__ uint32_t soff(int r, int k) {
    uint32_t u = (uint32_t)(k >> 3);
    uint32_t us = (u & 8u) | ((u ^ (uint32_t)(r & 7)) & 7u);
    return (uint32_t)r * 256u + us * 16u + (uint32_t)(k & 7) * 2u;
}

// Non-volatile (schedulable) ldmatrix with memory clobber.
__device__ __forceinline__ void ldsm_x4(uint32_t* r, uint32_t addr) {
    asm("ldmatrix.sync.aligned.m8n8.x4.shared.b16 {%0,%1,%2,%3}, [%4];"
        : "=r"(r[0]), "=r"(r[1]), "=r"(r[2]), "=r"(r[3]) : "r"(addr) : "memory");
}

__device__ __forceinline__ void mma16816(float* d, const uint32_t* a,
                                         uint32_t b0, uint32_t b1) {
    asm("mma.sync.aligned.m16n8k16.row.col.f32.bf16.bf16.f32 "
        "{%0,%1,%2,%3}, {%4,%5,%6,%7}, {%8,%9}, {%0,%1,%2,%3};"
        : "+f"(d[0]), "+f"(d[1]), "+f"(d[2]), "+f"(d[3])
        : "r"(a[0]), "r"(a[1]), "r"(a[2]), "r"(a[3]), "r"(b0), "r"(b1));
}

// ---------------- weight prep: fp32 W[k,n] -> swizzled bf16 hi/lo images -----
__global__ __launch_bounds__(256)
void prep_w_kernel(const float* __restrict__ W0, const float* __restrict__ W1,
                   const float* __restrict__ W2, const float* __restrict__ W3,
                   __nv_bfloat16* __restrict__ img1, __nv_bfloat16* __restrict__ img2) {
    int gi = blockIdx.x * 256 + threadIdx.x;
    if (gi >= 4 * DIM * DIM) return;
    int m = gi >> 14;
    int i = gi & (DIM * DIM - 1);
    const float* W = (m == 0) ? W0 : (m == 1) ? W1 : (m == 2) ? W2 : W3;
    int k = i >> 7;
    int n = i & 127;
    float a = W[i];
    __nv_bfloat16 h = __float2bfloat16(a);
    float lo = a - __bfloat162float(h);
    uint32_t off = soff(n, k);
    *(__nv_bfloat16*)((char*)(img1 + (size_t)m * DIM * DIM) + off) = h;
    *(__nv_bfloat16*)((char*)(img2 + (size_t)m * DIM * DIM) + off) = __float2bfloat16(lo);
}

// ----------- persistent pipelined HMMA GEMM: C[M,128] = X[M,128]@W + b ------
// 512 threads, 16 warps in 4(M)x4(N) grid, 32x32 warp tiles.
// smem: bias 1K | A[2] 128K (each: A1 32K + A2 32K) | W1 32K | W2 32K = 193K
#define SM_BIAS  0
#define SM_ABUF  1024
#define SM_W1    (1024 + 131072)
#define SM_W2    (1024 + 131072 + 32768)
#define SM_TOTAL (1024 + 131072 + 65536)
#define GTHREADS 512

__global__ __launch_bounds__(GTHREADS, 1)
void gemm_mma_kernel(const float* __restrict__ X,
                     const __nv_bfloat16* __restrict__ W1img,
                     const __nv_bfloat16* __restrict__ W2img,
                     const float* __restrict__ bias,
                     float* __restrict__ C, int M, int nT) {
    extern __shared__ char smem[];
    const uint32_t sb = smem_u32(smem);
    const int tid = threadIdx.x;
    const int wid = tid >> 5;
    const int lid = tid & 31;

    // ---- one-time: weights + bias into smem ----
    {
        const int4* s1 = (const int4*)W1img;
        const int4* s2 = (const int4*)W2img;
        int4* d1 = (int4*)(smem + SM_W1);
        int4* d2 = (int4*)(smem + SM_W2);
        #pragma unroll
        for (int i = tid; i < 2048; i += GTHREADS) {
            d1[i] = s1[i];
            d2[i] = s2[i];
        }
    }
    if (tid < 128) *(float*)(smem + SM_BIAS + tid * 4) = bias[tid];

    // ---- per-thread convert slots (tile-invariant): j = tid + w*512 ----
    uint32_t preoff[8];   // swizzled byte offset within A1/A2 tile
    int      xoff[8];     // element offset within a 128-row fp32 tile
    #pragma unroll
    for (int w = 0; w < 8; w++) {
        int j  = tid + w * GTHREADS;
        int r  = j >> 5;
        int k4 = (j & 31) << 2;
        preoff[w] = soff(r, k4);
        xoff[w]   = r * DIM + k4;
    }

    // LDG one wave (4 slots) of tile t into vb
    auto ldg_wave = [&](int t, int w0, float4* vb) {
        const size_t base = (size_t)t * 128 * DIM;
        const int lim = (M - t * 128) * DIM;
        #pragma unroll
        for (int i = 0; i < 4; i++) {
            int w = w0 + i;
            vb[i] = (xoff[w] < lim) ? *(const float4*)(X + base + xoff[w])
                                    : make_float4(0.f, 0.f, 0.f, 0.f);
        }
    };
    // convert one wave into A buffer at byte base abuf (A1 at +0, A2 at +32768)
    auto cvt_wave = [&](char* abuf, int w0, const float4* vb) {
        #pragma unroll
        for (int i = 0; i < 4; i++) {
            int w = w0 + i;
            float4 v = vb[i];
            __nv_bfloat162 hp0 = __floats2bfloat162_rn(v.x, v.y);
            __nv_bfloat162 hp1 = __floats2bfloat162_rn(v.z, v.w);
            __nv_bfloat162 lp0 = __floats2bfloat162_rn(v.x - __bfloat162float(hp0.x),
                                                       v.y - __bfloat162float(hp0.y));
            __nv_bfloat162 lp1 = __floats2bfloat162_rn(v.z - __bfloat162float(hp1.x),
                                                       v.w - __bfloat162float(hp1.y));
            uint2 hq, lq;
            hq.x = *(uint32_t*)&hp0; hq.y = *(uint32_t*)&hp1;
            lq.x = *(uint32_t*)&lp0; lq.y = *(uint32_t*)&lp1;
            *(uint2*)(abuf + preoff[w])         = hq;
            *(uint2*)(abuf + 32768 + preoff[w]) = lq;
        }
    };

    const int wm = (wid >> 2) * 32;
    const int wn = (wid & 3) * 32;
    const int g  = lid >> 3;
    const int lr = (lid & 7) | ((g & 1) << 3);
    const int kq = (g >> 1) << 3;
    const int cr = lid >> 2;
    const int cc = (lid & 3) * 2;
    const float* sBias = (const float*)(smem + SM_BIAS);

    // prologue: convert first tile into buf 0
    if ((int)blockIdx.x < nT) {
        float4 vb[4];
        ldg_wave(blockIdx.x, 0, vb);
        cvt_wave(smem + SM_ABUF, 0, vb);
        ldg_wave(blockIdx.x, 4, vb);
        cvt_wave(smem + SM_ABUF, 4, vb);
    }
    __syncthreads();

    int pb = 0;
    for (int t = blockIdx.x; t < nT; t += gridDim.x, pb ^= 1) {
        const uint32_t cur = sb + SM_ABUF + (uint32_t)pb * 65536u;
        char* nxt = smem + SM_ABUF + (pb ^ 1) * 65536;
        const int tn = t + gridDim.x;
        const bool hn = tn < nT;

        float acc[2][4][4];
        #pragma unroll
        for (int i = 0; i < 2; i++)
            #pragma unroll
            for (int j = 0; j < 4; j++)
                #pragma unroll
                for (int u = 0; u < 4; u++) acc[i][j][u] = 0.f;

        float4 vb[4];
        if (hn) ldg_wave(tn, 0, vb);

        // ---- MMA halves with convert interleaved ----
        #pragma unroll
        for (int half = 0; half < 2; half++) {
            #pragma unroll
            for (int ks = half * 4; ks < half * 4 + 4; ks++) {
                const int k0 = ks * 16 + kq;
                uint32_t a1f[2][4], a2f[2][4], b1f[2][4], b2f[2][4];
                #pragma unroll
                for (int mt = 0; mt < 2; mt++) {
                    ldsm_x4(a1f[mt], cur + soff(wm + mt * 16 + lr, k0));
                    ldsm_x4(a2f[mt], cur + 32768u + soff(wm + mt * 16 + lr, k0));
                }
                #pragma unroll
                for (int nt2 = 0; nt2 < 2; nt2++) {
                    ldsm_x4(b1f[nt2], sb + SM_W1 + soff(wn + nt2 * 16 + lr, k0));
                    ldsm_x4(b2f[nt2], sb + SM_W2 + soff(wn + nt2 * 16 + lr, k0));
                }
                // term-major order: same-acc reuse distance = 8
                #pragma unroll
                for (int mt = 0; mt < 2; mt++) {
                    mma16816(acc[mt][0], a1f[mt], b1f[0][0], b1f[0][2]);
                    mma16816(acc[mt][1], a1f[mt], b1f[0][1], b1f[0][3]);
                    mma16816(acc[mt][2], a1f[mt], b1f[1][0], b1f[1][2]);
                    mma16816(acc[mt][3], a1f[mt], b1f[1][1], b1f[1][3]);
                }
                #pragma unroll
                for (int mt = 0; mt < 2; mt++) {
                    mma16816(acc[mt][0], a2f[mt], b1f[0][0], b1f[0][2]);
                    mma16816(acc[mt][1], a2f[mt], b1f[0][1], b1f[0][3]);
                    mma16816(acc[mt][2], a2f[mt], b1f[1][0], b1f[1][2]);
                    mma16816(acc[mt][3], a2f[mt], b1f[1][1], b1f[1][3]);
                }
                #pragma unroll
                for (int mt = 0; mt < 2; mt++) {
                    mma16816(acc[mt][0], a1f[mt], b2f[0][0], b2f[0][2]);
                    mma16816(acc[mt][1], a1f[mt], b2f[0][1], b2f[0][3]);
                    mma16816(acc[mt][2], a1f[mt], b2f[1][0], b2f[1][2]);
                    mma16816(acc[mt][3], a1f[mt], b2f[1][1], b2f[1][3]);
                }
            }
            // convert this wave into the other buffer; start next LDG wave
            if (hn) {
                cvt_wave(nxt, half * 4, vb);
                if (half == 0) ldg_wave(tn, 4, vb);
            }
        }

        // epilogue
        const int row0 = t * 128;
        #pragma unroll
        for (int mt = 0; mt < 2; mt++) {
            #pragma unroll
            for (int nt = 0; nt < 4; nt++) {
                int col = wn + nt * 8 + cc;
                float b0 = sBias[col], b1 = sBias[col + 1];
                int r1 = row0 + wm + mt * 16 + cr;
                if (r1 < M) {
                    float2 o; o.x = acc[mt][nt][0] + b0; o.y = acc[mt][nt][1] + b1;
                    *(float2*)(C + (size_t)r1 * DIM + col) = o;
                }
                int r2 = r1 + 8;
                if (r2 < M) {
                    float2 o; o.x = acc[mt][nt][2] + b0; o.y = acc[mt][nt][3] + b1;
                    *(float2*)(C + (size_t)r2 * DIM + col) = o;
                }
            }
        }
        __syncthreads();
    }
}

// --------------------------- edge scatter kernel ----------------------------
__device__ __forceinline__ void red4(float* p, float a, float b, float c, float d) {
    asm volatile("red.global.add.v4.f32 [%0], {%1, %2, %3, %4};"
                 :: "l"(p), "f"(a), "f"(b), "f"(c), "f"(d) : "memory");
}

__global__ __launch_bounds__(256)
void edge_kernel(const int* __restrict__ ei, const float* __restrict__ E,
                 float* __restrict__ wV, int nE) {
    const int lid   = threadIdx.x & 31;
    const int warp  = (blockIdx.x * blockDim.x + threadIdx.x) >> 5;
    const int nwarp = (gridDim.x * blockDim.x) >> 5;
    const int h  = lid >> 2;
    const int i4 = lid & 3;

    for (int e = warp; e < nE; e += nwarp) {
        int src = __ldg(ei + e);
        int dst = __ldg(ei + nE + e);

        float4 k  = *(const float4*)(g_K + (size_t)src * DIM + 4 * lid);
        float4 q  = *(const float4*)(g_Q + (size_t)dst * DIM + 4 * lid);
        float4 ev = __ldg((const float4*)(E + (size_t)e * DIM + 4 * lid));

        float t = k.x * q.x * ev.x + k.y * q.y * ev.y
                + k.z * q.z * ev.z + k.w * q.w * ev.w;
        t += __shfl_xor_sync(0xFFFFFFFFu, t, 1);
        t += __shfl_xor_sync(0xFFFFFFFFu, t, 2);
        t *= 0.25f;                          // 1/sqrt(16)
        t = fminf(fmaxf(t, -5.f), 5.f);
        float s = __expf(t);

        float4 v = *(const float4*)(g_V + (size_t)src * DIM + 4 * lid);
        red4(wV + (size_t)dst * DIM + 4 * lid, v.x * s, v.y * s, v.z * s, v.w * s);
        if (i4 == 0) atomicAdd(&g_Z[dst * NH + h], s);
    }
}

// ----------------------------- normalize ------------------------------------
__global__ __launch_bounds__(256)
void normalize_kernel(float* __restrict__ out, int n) {
    int i = blockIdx.x * blockDim.x + threadIdx.x;
    if (i >= n) return;
    int node = i >> 7;
    int h    = (i >> 4) & 7;
    float z = g_Z[node * NH + h];
    out[i] = out[i] / (z + 1e-6f);
}

// ----------------------------- launcher -------------------------------------
extern "C" void kernel_launch(void* const* d_in, const int* in_sizes, int n_in,
                              void* d_out, int out_size) {
    const float* x   = (const float*)d_in[0];
    const float* ea  = (const float*)d_in[1];
    const int*   ei  = (const int*)d_in[2];
    const float* Wq  = (const float*)d_in[3];
    const float* bq  = (const float*)d_in[4];
    const float* Wk  = (const float*)d_in[5];
    const float* bk  = (const float*)d_in[6];
    const float* We  = (const float*)d_in[7];
    const float* be  = (const float*)d_in[8];
    const float* Wv  = (const float*)d_in[9];
    const float* bv  = (const float*)d_in[10];
    float* out = (float*)d_out;

    const int nN = in_sizes[0] / DIM;     // 50000
    const int nE = in_sizes[1] / DIM;     // 800000

    float *pQ, *pK, *pV, *pE, *pZ;
    __nv_bfloat16 *pW1, *pW2;
    cudaGetSymbolAddress((void**)&pQ, g_Q);
    cudaGetSymbolAddress((void**)&pK, g_K);
    cudaGetSymbolAddress((void**)&pV, g_V);
    cudaGetSymbolAddress((void**)&pE, g_E);
    cudaGetSymbolAddress((void**)&pZ, g_Z);
    cudaGetSymbolAddress((void**)&pW1, g_W1img);
    cudaGetSymbolAddress((void**)&pW2, g_W2img);

    cudaMemsetAsync(d_out, 0, (size_t)out_size * sizeof(float));
    cudaMemsetAsync(pZ, 0, (size_t)nN * NH * sizeof(float));

    prep_w_kernel<<<(4 * DIM * DIM + 255) / 256, 256>>>(Wq, Wk, Wv, We, pW1, pW2);

    cudaFuncSetAttribute(gemm_mma_kernel, cudaFuncAttributeMaxDynamicSharedMemorySize, SM_TOTAL);

    int tN = (nN + 127) / 128;    // 391
    int tE = (nE + 127) / 128;    // 6250
    int gN = tN < 148 ? tN : 148;
    gemm_mma_kernel<<<gN, GTHREADS, SM_TOTAL>>>(x,  pW1 + 0 * DIM * DIM, pW2 + 0 * DIM * DIM, bq, pQ, nN, tN);
    gemm_mma_kernel<<<gN, GTHREADS, SM_TOTAL>>>(x,  pW1 + 1 * DIM * DIM, pW2 + 1 * DIM * DIM, bk, pK, nN, tN);
    gemm_mma_kernel<<<gN, GTHREADS, SM_TOTAL>>>(x,  pW1 + 2 * DIM * DIM, pW2 + 2 * DIM * DIM, bv, pV, nN, tN);
    gemm_mma_kernel<<<148, GTHREADS, SM_TOTAL>>>(ea, pW1 + 3 * DIM * DIM, pW2 + 3 * DIM * DIM, be, pE, nE, tE);

    edge_kernel<<<4096, 256>>>(ei, pE, out, nE);

    int totalO = nN * DIM;
    normalize_kernel<<<(totalO + 255) / 256, 256>>>(out, totalO);
}